// round 4
// baseline (speedup 1.0000x reference)
#include <cuda_runtime.h>
#include <math.h>

// Problem constants
#define D_MODEL 1024
#define H_HEADS 16
#define HD      64
#define B_BATCH 2
#define S_SEQ   2048
#define M_ROWS  (B_BATCH * S_SEQ)      // 4096
#define QKV_N   (3 * D_MODEL)          // 3072

// Scratch (device globals — allocation-free)
__device__ float g_qkv [M_ROWS * QKV_N];    // [B*S, 3D]
__device__ float g_attn[M_ROWS * D_MODEL];  // [B*S, D]

// ---------------------------------------------------------------------------
// SGEMM with bias: C[M,N] = A[M,K] @ B[K,N] + bias[N]
// 128x128 block tile, BK=8, 256 threads, 8x8 per-thread microtile.
// M,N,K all multiples of 128/128/8 for this problem -> no bounds checks.
// ---------------------------------------------------------------------------
__global__ __launch_bounds__(256, 2)
void sgemm_bias_kernel(const float* __restrict__ A,
                       const float* __restrict__ Bm,
                       const float* __restrict__ bias,
                       float* __restrict__ C,
                       int M, int N, int K)
{
    __shared__ float As[8][132];   // transposed A tile, padded (conflict-free)
    __shared__ float Bs[8][128];

    const int tid = threadIdx.x;
    const int bm  = blockIdx.y;
    const int bn  = blockIdx.x;

    const int tr = tid >> 4;       // 0..15 (thread row)
    const int tc = tid & 15;       // 0..15 (thread col)

    // Global load mapping
    const int aRow = tid >> 1;            // 0..127
    const int aCol = (tid & 1) * 4;       // 0 or 4
    const int bRow = tid >> 5;            // 0..7
    const int bCol = (tid & 31) * 4;      // 0..124

    const float* Aptr = A  + (size_t)(bm * 128 + aRow) * K + aCol;
    const float* Bptr = Bm + (size_t)bRow * N + bn * 128 + bCol;

    float acc[8][8];
    #pragma unroll
    for (int i = 0; i < 8; ++i)
        #pragma unroll
        for (int j = 0; j < 8; ++j) acc[i][j] = 0.0f;

    for (int k0 = 0; k0 < K; k0 += 8) {
        const float4 a4 = *(const float4*)(Aptr + k0);
        const float4 b4 = *(const float4*)(Bptr + (size_t)k0 * N);

        As[aCol + 0][aRow] = a4.x;
        As[aCol + 1][aRow] = a4.y;
        As[aCol + 2][aRow] = a4.z;
        As[aCol + 3][aRow] = a4.w;
        *(float4*)&Bs[bRow][bCol] = b4;
        __syncthreads();

        #pragma unroll
        for (int k = 0; k < 8; ++k) {
            float ra[8], rb[8];
            *(float4*)&ra[0] = *(const float4*)&As[k][tr * 8];
            *(float4*)&ra[4] = *(const float4*)&As[k][tr * 8 + 4];
            *(float4*)&rb[0] = *(const float4*)&Bs[k][tc * 8];
            *(float4*)&rb[4] = *(const float4*)&Bs[k][tc * 8 + 4];
            #pragma unroll
            for (int i = 0; i < 8; ++i)
                #pragma unroll
                for (int j = 0; j < 8; ++j)
                    acc[i][j] += ra[i] * rb[j];
        }
        __syncthreads();
    }

    // Epilogue: add bias, vectorized stores
    float rbias[8];
    *(float4*)&rbias[0] = *(const float4*)(bias + bn * 128 + tc * 8);
    *(float4*)&rbias[4] = *(const float4*)(bias + bn * 128 + tc * 8 + 4);

    #pragma unroll
    for (int i = 0; i < 8; ++i) {
        float* crow = C + (size_t)(bm * 128 + tr * 8 + i) * N + bn * 128 + tc * 8;
        float4 o0, o1;
        o0.x = acc[i][0] + rbias[0];  o0.y = acc[i][1] + rbias[1];
        o0.z = acc[i][2] + rbias[2];  o0.w = acc[i][3] + rbias[3];
        o1.x = acc[i][4] + rbias[4];  o1.y = acc[i][5] + rbias[5];
        o1.z = acc[i][6] + rbias[6];  o1.w = acc[i][7] + rbias[7];
        *(float4*)(crow)     = o0;
        *(float4*)(crow + 4) = o1;
    }
}

// ---------------------------------------------------------------------------
// Flash attention, fp32. Br = Bc = 64, HD = 64. One block per (q-tile, h, b).
// 256 threads, 16x16 thread grid, 4x4 microtiles for both S=QK^T and O=PV.
// Q and K tiles stored with a 16B-granular XOR swizzle so both the
// global->smem float4 stores and the inner-loop float4 reads are ~conflict-
// free without padding; exactly 48KB static smem (3 x 64x64 fp32 tiles,
// P tile reuses the K buffer).
// ---------------------------------------------------------------------------
__device__ __forceinline__ int swz(int row, int d4) {
    // physical float offset of the 4-float quad (row, d4) in a 64x64 tile
    return row * 64 + (((d4 ^ (row >> 2)) & 15) << 2);
}

__global__ __launch_bounds__(256)
void flash_attn_kernel(const float* __restrict__ qkv, float* __restrict__ out)
{
    __shared__ float Qs[64 * 64];
    __shared__ float Ks[64 * 64];   // reused as P tile after scores are done
    __shared__ float Vs[64 * 64];

    const int tid = threadIdx.x;
    const int ty  = tid >> 4;      // 0..15 -> query rows ty*4 .. ty*4+3
    const int tx  = tid & 15;      // 0..15 -> key/value cols tx*4 .. tx*4+3
    const int qt  = blockIdx.x;    // q tile 0..31
    const int h   = blockIdx.y;    // head
    const int b   = blockIdx.z;    // batch

    const int RS = 3 * D_MODEL;    // qkv row stride (3072)
    const float* qbase = qkv + ((size_t)b * S_SEQ + (size_t)qt * 64) * RS + h * HD;
    const float* kbase = qkv + ((size_t)b * S_SEQ) * RS + D_MODEL + h * HD;
    const float* vbase = kbase + D_MODEL;

    // Loader mapping: 4 passes, each warp covers 2 rows of 64 floats (coalesced)
    const int lr = tid >> 4;       // row base 0..15
    const int lq = tid & 15;       // quad index (d = lq*4)

    // Load Q tile, pre-scaled by 1/sqrt(HD) = 0.125
    #pragma unroll
    for (int p = 0; p < 4; ++p) {
        const int r = lr + p * 16;
        float4 v = *(const float4*)(qbase + (size_t)r * RS + lq * 4);
        v.x *= 0.125f; v.y *= 0.125f; v.z *= 0.125f; v.w *= 0.125f;
        *(float4*)&Qs[swz(r, lq)] = v;
    }

    float m[4], l[4], o[4][4];
    #pragma unroll
    for (int i = 0; i < 4; ++i) {
        m[i] = -1e30f; l[i] = 0.0f;
        #pragma unroll
        for (int j = 0; j < 4; ++j) o[i][j] = 0.0f;
    }

    for (int t = 0; t < S_SEQ / 64; ++t) {
        __syncthreads();   // previous tile's P/V reads done; Q visible at t=0

        // Load K (swizzled) and V (plain row-major) tiles
        #pragma unroll
        for (int p = 0; p < 4; ++p) {
            const int r = lr + p * 16;
            const size_t g = (size_t)(t * 64 + r) * RS + lq * 4;
            const float4 k4 = *(const float4*)(kbase + g);
            const float4 v4 = *(const float4*)(vbase + g);
            *(float4*)&Ks[swz(r, lq)]     = k4;
            *(float4*)&Vs[r * 64 + lq * 4] = v4;
        }
        __syncthreads();

        // ---- S = (Q*scale) @ K^T  (4x4 microtile per thread) ----
        float s[4][4];
        #pragma unroll
        for (int i = 0; i < 4; ++i)
            #pragma unroll
            for (int j = 0; j < 4; ++j) s[i][j] = 0.0f;

        #pragma unroll 4
        for (int d4 = 0; d4 < 16; ++d4) {
            float4 qv[4], kv[4];
            #pragma unroll
            for (int i = 0; i < 4; ++i)
                qv[i] = *(const float4*)&Qs[swz(ty * 4 + i, d4)];
            #pragma unroll
            for (int j = 0; j < 4; ++j)
                kv[j] = *(const float4*)&Ks[swz(tx * 4 + j, d4)];
            #pragma unroll
            for (int i = 0; i < 4; ++i)
                #pragma unroll
                for (int j = 0; j < 4; ++j)
                    s[i][j] += qv[i].x * kv[j].x + qv[i].y * kv[j].y
                             + qv[i].z * kv[j].z + qv[i].w * kv[j].w;
        }

        // ---- online softmax (row stats reduced across the 16 tx lanes) ----
        float p_[4][4];
        #pragma unroll
        for (int i = 0; i < 4; ++i) {
            float tm = s[i][0];
            #pragma unroll
            for (int j = 1; j < 4; ++j) tm = fmaxf(tm, s[i][j]);
            #pragma unroll
            for (int off = 8; off >= 1; off >>= 1)
                tm = fmaxf(tm, __shfl_xor_sync(0xffffffffu, tm, off));

            const float mn    = fmaxf(m[i], tm);
            const float alpha = __expf(m[i] - mn);
            m[i] = mn;

            float rs = 0.0f;
            #pragma unroll
            for (int j = 0; j < 4; ++j) {
                p_[i][j] = __expf(s[i][j] - mn);
                rs += p_[i][j];
            }
            #pragma unroll
            for (int off = 8; off >= 1; off >>= 1)
                rs += __shfl_xor_sync(0xffffffffu, rs, off);

            l[i] = l[i] * alpha + rs;
            #pragma unroll
            for (int j = 0; j < 4; ++j) o[i][j] *= alpha;
        }

        __syncthreads();   // everyone done reading Ks (scores complete)

        // Write P into the K buffer (plain row-major [64][64])
        #pragma unroll
        for (int i = 0; i < 4; ++i)
            *(float4*)&Ks[(ty * 4 + i) * 64 + tx * 4] =
                make_float4(p_[i][0], p_[i][1], p_[i][2], p_[i][3]);
        __syncthreads();

        // ---- O += P @ V ----
        #pragma unroll 4
        for (int c4 = 0; c4 < 16; ++c4) {
            float4 pv[4];
            #pragma unroll
            for (int i = 0; i < 4; ++i)
                pv[i] = *(const float4*)&Ks[(ty * 4 + i) * 64 + c4 * 4];
            #pragma unroll
            for (int cc = 0; cc < 4; ++cc) {
                const float4 vv = *(const float4*)&Vs[(c4 * 4 + cc) * 64 + tx * 4];
                #pragma unroll
                for (int i = 0; i < 4; ++i) {
                    const float pc = ((const float*)&pv[i])[cc];
                    o[i][0] += pc * vv.x;
                    o[i][1] += pc * vv.y;
                    o[i][2] += pc * vv.z;
                    o[i][3] += pc * vv.w;
                }
            }
        }
    }

    // ---- epilogue: normalize and write [B,S,D] with D index = h*64 + dv ----
    float* obase = out + ((size_t)b * S_SEQ + (size_t)qt * 64) * D_MODEL + h * HD;
    #pragma unroll
    for (int i = 0; i < 4; ++i) {
        const float inv = __fdividef(1.0f, l[i]);
        const int r = ty * 4 + i;
        const float4 res = make_float4(o[i][0] * inv, o[i][1] * inv,
                                       o[i][2] * inv, o[i][3] * inv);
        *(float4*)(obase + (size_t)r * D_MODEL + tx * 4) = res;
    }
}

// ---------------------------------------------------------------------------
// Launch
// ---------------------------------------------------------------------------
extern "C" void kernel_launch(void* const* d_in, const int* in_sizes, int n_in,
                              void* d_out, int out_size)
{
    const float* x     = (const float*)d_in[0];
    const float* W_qkv = (const float*)d_in[1];
    const float* b_qkv = (const float*)d_in[2];
    const float* W_out = (const float*)d_in[3];
    const float* b_out = (const float*)d_in[4];
    float* out = (float*)d_out;

    float* qkv_s;
    float* attn_s;
    cudaGetSymbolAddress((void**)&qkv_s,  g_qkv);
    cudaGetSymbolAddress((void**)&attn_s, g_attn);

    const dim3 blk(256);

    // 1) QKV projection: [4096,1024] @ [1024,3072] + b  -> g_qkv
    sgemm_bias_kernel<<<dim3(QKV_N / 128, M_ROWS / 128), blk>>>(
        x, W_qkv, b_qkv, qkv_s, M_ROWS, QKV_N, D_MODEL);

    // 2) Flash attention per (q-tile, head, batch) -> g_attn
    flash_attn_kernel<<<dim3(S_SEQ / 64, H_HEADS, B_BATCH), blk>>>(qkv_s, attn_s);

    // 3) Output projection: [4096,1024] @ [1024,1024] + b -> out
    sgemm_bias_kernel<<<dim3(D_MODEL / 128, M_ROWS / 128), blk>>>(
        attn_s, W_out, b_out, out, M_ROWS, D_MODEL, D_MODEL);
}

// round 7
// speedup vs baseline: 1.4374x; 1.4374x over previous
#include <cuda_runtime.h>
#include <cuda_bf16.h>
#include <math.h>
#include <stdint.h>

// ---------------------------------------------------------------------------
// Problem constants
// ---------------------------------------------------------------------------
#define D_MODEL 1024
#define H_HEADS 16
#define HD      64
#define B_BATCH 2
#define S_SEQ   2048
#define M_ROWS  (B_BATCH * S_SEQ)      // 4096
#define QKV_N   (3 * D_MODEL)          // 3072
#define KSPLIT  (3 * D_MODEL)          // split-K: [hi | lo | hi] of K=1024

// ---------------------------------------------------------------------------
// Scratch (device globals — allocation-free)
// ---------------------------------------------------------------------------
__device__ __align__(256) float         g_qkv [M_ROWS * QKV_N];     // fp32 qkv
__device__ __align__(256) float         g_attn[M_ROWS * D_MODEL];   // fp32 attn
__device__ __align__(256) __nv_bfloat16 g_Abf [M_ROWS * KSPLIT];    // A' split
__device__ __align__(256) __nv_bfloat16 g_Bqkv[QKV_N  * KSPLIT];    // W_qkv^T split
__device__ __align__(256) __nv_bfloat16 g_Bout[D_MODEL * KSPLIT];   // W_out^T split

// ---------------------------------------------------------------------------
// Helpers (portable PTX only: ldmatrix / mma.sync / cp.async — no tcgen05)
// ---------------------------------------------------------------------------
__device__ __forceinline__ uint32_t smem_to_u32(const void* p) {
    uint32_t a;
    asm("{ .reg .u64 t; cvta.to.shared.u64 t, %1; cvt.u32.u64 %0, t; }"
        : "=r"(a) : "l"(p));
    return a;
}
__device__ __forceinline__ void cp_async16(uint32_t dst, const void* src) {
    asm volatile("cp.async.cg.shared.global [%0], [%1], 16;" :: "r"(dst), "l"(src));
}
__device__ __forceinline__ void cp_commit() { asm volatile("cp.async.commit_group;"); }
__device__ __forceinline__ void cp_wait1()  { asm volatile("cp.async.wait_group 1;"); }

__device__ __forceinline__ void ldsm_x4(uint32_t& r0, uint32_t& r1,
                                        uint32_t& r2, uint32_t& r3, uint32_t addr) {
    asm volatile("ldmatrix.sync.aligned.m8n8.x4.shared.b16 {%0,%1,%2,%3}, [%4];"
                 : "=r"(r0), "=r"(r1), "=r"(r2), "=r"(r3) : "r"(addr));
}
__device__ __forceinline__ void mma16816(float* c, const uint32_t* a, const uint32_t* b) {
    asm volatile("mma.sync.aligned.m16n8k16.row.col.f32.bf16.bf16.f32 "
                 "{%0,%1,%2,%3}, {%4,%5,%6,%7}, {%8,%9}, {%0,%1,%2,%3};"
                 : "+f"(c[0]), "+f"(c[1]), "+f"(c[2]), "+f"(c[3])
                 : "r"(a[0]), "r"(a[1]), "r"(a[2]), "r"(a[3]),
                   "r"(b[0]), "r"(b[1]));
}

// Swizzled byte offset of (row r, byte b within 128B row); XOR on 16B chunks
// -> every 8-row ldmatrix phase hits 8 distinct 16B bank groups.
#define SWZ(r, b) ((r) * 128 + ((b) ^ (((r) & 7) << 4)))

// ---------------------------------------------------------------------------
// Split conversions: fp32 -> bf16 [hi | lo | hi] along K (K = 1024)
// ---------------------------------------------------------------------------
__global__ void split_hi_lo_kernel(const float* __restrict__ in,
                                   __nv_bfloat16* __restrict__ out)
{
    int idx = blockIdx.x * blockDim.x + threadIdx.x;   // one float4 per thread
    int m  = idx >> 8;          // 256 float4 per 1024-row
    int c4 = idx & 255;
    float4 v = *(const float4*)(in + ((size_t)m << 10) + c4 * 4);
    float vv[4] = {v.x, v.y, v.z, v.w};
    __nv_bfloat16 h[4], l[4];
    #pragma unroll
    for (int i = 0; i < 4; ++i) {
        h[i] = __float2bfloat16(vv[i]);
        l[i] = __float2bfloat16(vv[i] - __bfloat162float(h[i]));
    }
    __nv_bfloat16* base = out + (size_t)m * KSPLIT + c4 * 4;
    *(__nv_bfloat162*)(base + 0)    = __halves2bfloat162(h[0], h[1]);
    *(__nv_bfloat162*)(base + 2)    = __halves2bfloat162(h[2], h[3]);
    *(__nv_bfloat162*)(base + 1024) = __halves2bfloat162(l[0], l[1]);
    *(__nv_bfloat162*)(base + 1026) = __halves2bfloat162(l[2], l[3]);
    *(__nv_bfloat162*)(base + 2048) = __halves2bfloat162(h[0], h[1]);
    *(__nv_bfloat162*)(base + 2050) = __halves2bfloat162(h[2], h[3]);
}

// W [K=1024, N] row-major -> B' [N, 3K] bf16: [hi | hi | lo]
__global__ void transpose_split_kernel(const float* __restrict__ W,
                                       __nv_bfloat16* __restrict__ out, int N)
{
    __shared__ float tile[32][33];
    const int n0 = blockIdx.x * 32, k0 = blockIdx.y * 32;
    const int tx = threadIdx.x, ty = threadIdx.y;   // (32, 8)
    #pragma unroll
    for (int i = 0; i < 4; ++i)
        tile[ty + i * 8][tx] = W[(size_t)(k0 + ty + i * 8) * N + n0 + tx];
    __syncthreads();
    #pragma unroll
    for (int i = 0; i < 4; ++i) {
        const int n = n0 + ty + i * 8;
        const int k = k0 + tx;
        const float v = tile[tx][ty + i * 8];
        const __nv_bfloat16 h = __float2bfloat16(v);
        const __nv_bfloat16 l = __float2bfloat16(v - __bfloat162float(h));
        __nv_bfloat16* row = out + (size_t)n * KSPLIT;
        row[k]               = h;
        row[D_MODEL + k]     = h;
        row[2 * D_MODEL + k] = l;
    }
}

// ---------------------------------------------------------------------------
// Tensor-core GEMM via mma.sync (HMMA):
//   C[M,N] = A'[M,K'] · B'[N,K']^T + bias, fp32 accumulate.
// CTA 128x128, BK=64 bf16 (128B rows, XOR-swizzled), 2-stage cp.async.
// 8 warps, each computing a 32x64 warp tile (2 x m16, 8 x n8 fragments).
// ---------------------------------------------------------------------------
#define BM 128
#define BN 128
#define BK 64
#define NCHUNK (KSPLIT / BK)                  // 48
#define STAGE_BYTES (BM * 128 + BN * 128)     // 32768
#define GEMM_SMEM (2 * STAGE_BYTES)           // 65536

__global__ __launch_bounds__(256)
void gemm_bf16_mma(const __nv_bfloat16* __restrict__ A,
                   const __nv_bfloat16* __restrict__ B,
                   const float* __restrict__ bias,
                   float* __restrict__ C, int N)
{
    extern __shared__ char smem[];
    const uint32_t sb = smem_to_u32(smem);
    const int tid  = threadIdx.x;
    const int wid  = tid >> 5, lane = tid & 31;
    const int wm   = wid & 3;           // 4 warps along M (32 rows each)
    const int wn   = wid >> 2;          // 2 warps along N (64 cols each)
    const int m0   = blockIdx.y * BM;
    const int n0   = blockIdx.x * BN;

    const __nv_bfloat16* Ab = A + (size_t)m0 * KSPLIT;
    const __nv_bfloat16* Bb = B + (size_t)n0 * KSPLIT;

    auto load_stage = [&](int kc, int s) {
        const uint32_t ab = sb + s * STAGE_BYTES;
        const uint32_t bb = ab + BM * 128;
        const int koff = kc * BK;
        #pragma unroll
        for (int p = 0; p < 4; ++p) {               // A: 128 rows x 8 chunks
            const int idx = tid + p * 256;
            const int r = idx >> 3, q = idx & 7;
            cp_async16(ab + r * 128 + ((q ^ (r & 7)) << 4),
                       Ab + (size_t)r * KSPLIT + koff + q * 8);
        }
        #pragma unroll
        for (int p = 0; p < 4; ++p) {               // B: 128 rows x 8 chunks
            const int idx = tid + p * 256;
            const int r = idx >> 3, q = idx & 7;
            cp_async16(bb + r * 128 + ((q ^ (r & 7)) << 4),
                       Bb + (size_t)r * KSPLIT + koff + q * 8);
        }
    };

    float acc[2][8][4];
    #pragma unroll
    for (int mt = 0; mt < 2; ++mt)
        #pragma unroll
        for (int nt = 0; nt < 8; ++nt)
            #pragma unroll
            for (int i = 0; i < 4; ++i) acc[mt][nt][i] = 0.0f;

    load_stage(0, 0); cp_commit();
    load_stage(1, 1); cp_commit();

    for (int kc = 0; kc < NCHUNK; ++kc) {
        const int s = kc & 1;
        cp_wait1();
        __syncthreads();

        const uint32_t ab = sb + s * STAGE_BYTES;
        const uint32_t bb = ab + BM * 128;

        #pragma unroll
        for (int ks = 0; ks < 4; ++ks) {            // 4 x k16 per BK=64
            const int kb = ks * 32;                 // byte offset of k0 in row

            // A fragments: 2 x m16k16 (ldmatrix.x4 each)
            uint32_t av[2][4];
            #pragma unroll
            for (int mt = 0; mt < 2; ++mt) {
                const int r  = wm * 32 + mt * 16 + (lane & 15);
                const int cb = kb + ((lane >> 4) << 4);
                ldsm_x4(av[mt][0], av[mt][1], av[mt][2], av[mt][3],
                        ab + SWZ(r, cb));
            }
            // B fragments: 8 x k16n8 (2 tiles per ldmatrix.x4)
            uint32_t bv[8][2];
            #pragma unroll
            for (int nt2 = 0; nt2 < 4; ++nt2) {
                const int r  = wn * 64 + nt2 * 16 + (lane & 7) + ((lane >> 4) << 3);
                const int cb = kb + (((lane >> 3) & 1) << 4);
                uint32_t t0, t1, t2, t3;
                ldsm_x4(t0, t1, t2, t3, bb + SWZ(r, cb));
                bv[nt2 * 2][0] = t0;  bv[nt2 * 2][1] = t1;
                bv[nt2 * 2 + 1][0] = t2;  bv[nt2 * 2 + 1][1] = t3;
            }
            #pragma unroll
            for (int mt = 0; mt < 2; ++mt)
                #pragma unroll
                for (int nt = 0; nt < 8; ++nt)
                    mma16816(acc[mt][nt], av[mt], bv[nt]);
        }

        __syncthreads();                            // all reads of stage s done
        if (kc + 2 < NCHUNK) load_stage(kc + 2, s);
        cp_commit();                                // uniform group count
    }

    // Epilogue: fragment layout c0,c1 -> (row g, col 2t..2t+1); c2,c3 -> row g+8
    const int g  = lane >> 2;
    const int tg = lane & 3;
    #pragma unroll
    for (int mt = 0; mt < 2; ++mt) {
        const int row0 = m0 + wm * 32 + mt * 16 + g;
        #pragma unroll
        for (int nt = 0; nt < 8; ++nt) {
            const int col = n0 + wn * 64 + nt * 8 + tg * 2;
            const float2 bv = *(const float2*)(bias + col);
            float2 v0, v1;
            v0.x = acc[mt][nt][0] + bv.x;  v0.y = acc[mt][nt][1] + bv.y;
            v1.x = acc[mt][nt][2] + bv.x;  v1.y = acc[mt][nt][3] + bv.y;
            *(float2*)(C + (size_t)row0 * N + col)       = v0;
            *(float2*)(C + (size_t)(row0 + 8) * N + col) = v1;
        }
    }
}

// ---------------------------------------------------------------------------
// Flash attention, fp32 (unchanged from passing R3 kernel)
// ---------------------------------------------------------------------------
__device__ __forceinline__ int swz(int row, int d4) {
    return row * 64 + (((d4 ^ (row >> 2)) & 15) << 2);
}

__global__ __launch_bounds__(256)
void flash_attn_kernel(const float* __restrict__ qkv, float* __restrict__ out)
{
    __shared__ float Qs[64 * 64];
    __shared__ float Ks[64 * 64];   // reused as P tile
    __shared__ float Vs[64 * 64];

    const int tid = threadIdx.x;
    const int ty  = tid >> 4;
    const int tx  = tid & 15;
    const int qt  = blockIdx.x;
    const int h   = blockIdx.y;
    const int b   = blockIdx.z;

    const int RS = 3 * D_MODEL;
    const float* qbase = qkv + ((size_t)b * S_SEQ + (size_t)qt * 64) * RS + h * HD;
    const float* kbase = qkv + ((size_t)b * S_SEQ) * RS + D_MODEL + h * HD;
    const float* vbase = kbase + D_MODEL;

    const int lr = tid >> 4;
    const int lq = tid & 15;

    #pragma unroll
    for (int p = 0; p < 4; ++p) {
        const int r = lr + p * 16;
        float4 v = *(const float4*)(qbase + (size_t)r * RS + lq * 4);
        v.x *= 0.125f; v.y *= 0.125f; v.z *= 0.125f; v.w *= 0.125f;
        *(float4*)&Qs[swz(r, lq)] = v;
    }

    float m[4], l[4], o[4][4];
    #pragma unroll
    for (int i = 0; i < 4; ++i) {
        m[i] = -1e30f; l[i] = 0.0f;
        #pragma unroll
        for (int j = 0; j < 4; ++j) o[i][j] = 0.0f;
    }

    for (int t = 0; t < S_SEQ / 64; ++t) {
        __syncthreads();

        #pragma unroll
        for (int p = 0; p < 4; ++p) {
            const int r = lr + p * 16;
            const size_t gg = (size_t)(t * 64 + r) * RS + lq * 4;
            const float4 k4 = *(const float4*)(kbase + gg);
            const float4 v4 = *(const float4*)(vbase + gg);
            *(float4*)&Ks[swz(r, lq)]      = k4;
            *(float4*)&Vs[r * 64 + lq * 4] = v4;
        }
        __syncthreads();

        float s[4][4];
        #pragma unroll
        for (int i = 0; i < 4; ++i)
            #pragma unroll
            for (int j = 0; j < 4; ++j) s[i][j] = 0.0f;

        #pragma unroll 4
        for (int d4 = 0; d4 < 16; ++d4) {
            float4 qv[4], kv[4];
            #pragma unroll
            for (int i = 0; i < 4; ++i)
                qv[i] = *(const float4*)&Qs[swz(ty * 4 + i, d4)];
            #pragma unroll
            for (int j = 0; j < 4; ++j)
                kv[j] = *(const float4*)&Ks[swz(tx * 4 + j, d4)];
            #pragma unroll
            for (int i = 0; i < 4; ++i)
                #pragma unroll
                for (int j = 0; j < 4; ++j)
                    s[i][j] += qv[i].x * kv[j].x + qv[i].y * kv[j].y
                             + qv[i].z * kv[j].z + qv[i].w * kv[j].w;
        }

        float p_[4][4];
        #pragma unroll
        for (int i = 0; i < 4; ++i) {
            float tm = s[i][0];
            #pragma unroll
            for (int j = 1; j < 4; ++j) tm = fmaxf(tm, s[i][j]);
            #pragma unroll
            for (int off = 8; off >= 1; off >>= 1)
                tm = fmaxf(tm, __shfl_xor_sync(0xffffffffu, tm, off));

            const float mn    = fmaxf(m[i], tm);
            const float alpha = __expf(m[i] - mn);
            m[i] = mn;

            float rs = 0.0f;
            #pragma unroll
            for (int j = 0; j < 4; ++j) {
                p_[i][j] = __expf(s[i][j] - mn);
                rs += p_[i][j];
            }
            #pragma unroll
            for (int off = 8; off >= 1; off >>= 1)
                rs += __shfl_xor_sync(0xffffffffu, rs, off);

            l[i] = l[i] * alpha + rs;
            #pragma unroll
            for (int j = 0; j < 4; ++j) o[i][j] *= alpha;
        }

        __syncthreads();

        #pragma unroll
        for (int i = 0; i < 4; ++i)
            *(float4*)&Ks[(ty * 4 + i) * 64 + tx * 4] =
                make_float4(p_[i][0], p_[i][1], p_[i][2], p_[i][3]);
        __syncthreads();

        #pragma unroll 4
        for (int c4 = 0; c4 < 16; ++c4) {
            float4 pv[4];
            #pragma unroll
            for (int i = 0; i < 4; ++i)
                pv[i] = *(const float4*)&Ks[(ty * 4 + i) * 64 + c4 * 4];
            #pragma unroll
            for (int cc = 0; cc < 4; ++cc) {
                const float4 vv = *(const float4*)&Vs[(c4 * 4 + cc) * 64 + tx * 4];
                #pragma unroll
                for (int i = 0; i < 4; ++i) {
                    const float pc = ((const float*)&pv[i])[cc];
                    o[i][0] += pc * vv.x;
                    o[i][1] += pc * vv.y;
                    o[i][2] += pc * vv.z;
                    o[i][3] += pc * vv.w;
                }
            }
        }
    }

    float* obase = out + ((size_t)b * S_SEQ + (size_t)qt * 64) * D_MODEL + h * HD;
    #pragma unroll
    for (int i = 0; i < 4; ++i) {
        const float inv = __fdividef(1.0f, l[i]);
        const int r = ty * 4 + i;
        const float4 res = make_float4(o[i][0] * inv, o[i][1] * inv,
                                       o[i][2] * inv, o[i][3] * inv);
        *(float4*)(obase + (size_t)r * D_MODEL + tx * 4) = res;
    }
}

// ---------------------------------------------------------------------------
// Launch
// ---------------------------------------------------------------------------
extern "C" void kernel_launch(void* const* d_in, const int* in_sizes, int n_in,
                              void* d_out, int out_size)
{
    const float* x     = (const float*)d_in[0];
    const float* W_qkv = (const float*)d_in[1];
    const float* b_qkv = (const float*)d_in[2];
    const float* W_out = (const float*)d_in[3];
    const float* b_out = (const float*)d_in[4];
    float* out = (float*)d_out;

    float *qkv_s, *attn_s;
    __nv_bfloat16 *Abf, *Bqkv, *Bout;
    cudaGetSymbolAddress((void**)&qkv_s,  g_qkv);
    cudaGetSymbolAddress((void**)&attn_s, g_attn);
    cudaGetSymbolAddress((void**)&Abf,    g_Abf);
    cudaGetSymbolAddress((void**)&Bqkv,   g_Bqkv);
    cudaGetSymbolAddress((void**)&Bout,   g_Bout);

    cudaFuncSetAttribute(gemm_bf16_mma,
                         cudaFuncAttributeMaxDynamicSharedMemorySize, GEMM_SMEM);

    // 1) split/convert inputs
    split_hi_lo_kernel<<<M_ROWS, 256>>>(x, Abf);
    transpose_split_kernel<<<dim3(QKV_N / 32, D_MODEL / 32), dim3(32, 8)>>>(W_qkv, Bqkv, QKV_N);
    transpose_split_kernel<<<dim3(D_MODEL / 32, D_MODEL / 32), dim3(32, 8)>>>(W_out, Bout, D_MODEL);

    // 2) QKV projection on tensor cores (HMMA): [4096,3072] fp32 + bias
    gemm_bf16_mma<<<dim3(QKV_N / BN, M_ROWS / BM), 256, GEMM_SMEM>>>(
        Abf, Bqkv, b_qkv, qkv_s, QKV_N);

    // 3) Flash attention (fp32 SIMT)
    flash_attn_kernel<<<dim3(S_SEQ / 64, H_HEADS, B_BATCH), 256>>>(qkv_s, attn_s);

    // 4) split attn output, then output projection on tensor cores
    split_hi_lo_kernel<<<M_ROWS, 256>>>(attn_s, Abf);
    gemm_bf16_mma<<<dim3(D_MODEL / BN, M_ROWS / BM), 256, GEMM_SMEM>>>(
        Abf, Bout, b_out, out, D_MODEL);
}

// round 8
// speedup vs baseline: 4.3267x; 3.0101x over previous
#include <cuda_runtime.h>
#include <cuda_bf16.h>
#include <math.h>
#include <stdint.h>

// ---------------------------------------------------------------------------
// Problem constants
// ---------------------------------------------------------------------------
#define D_MODEL 1024
#define H_HEADS 16
#define HD      64
#define B_BATCH 2
#define S_SEQ   2048
#define M_ROWS  (B_BATCH * S_SEQ)      // 4096
#define QKV_N   (3 * D_MODEL)          // 3072
#define KSPLIT  (3 * D_MODEL)          // split-K: [hi | lo | hi] of K=1024
#define QKV_E   (B_BATCH * H_HEADS * S_SEQ * HD)   // 4,194,304 per q/k/v

// ---------------------------------------------------------------------------
// Scratch (device globals — allocation-free)
// ---------------------------------------------------------------------------
__device__ __align__(256) float         g_attn[M_ROWS * D_MODEL];   // fp32 attn
__device__ __align__(256) __nv_bfloat16 g_Abf [M_ROWS * KSPLIT];    // A' split
__device__ __align__(256) __nv_bfloat16 g_Bqkv[QKV_N  * KSPLIT];    // W_qkv^T split
__device__ __align__(256) __nv_bfloat16 g_Bout[D_MODEL * KSPLIT];   // W_out^T split
__device__ __align__(256) __nv_bfloat16 g_qkvb[3 * QKV_E];          // bf16 q|k|v [B,H,S,64]

// ---------------------------------------------------------------------------
// Helpers (portable PTX only: ldmatrix / mma.sync / cp.async — no tcgen05)
// ---------------------------------------------------------------------------
__device__ __forceinline__ uint32_t smem_to_u32(const void* p) {
    uint32_t a;
    asm("{ .reg .u64 t; cvta.to.shared.u64 t, %1; cvt.u32.u64 %0, t; }"
        : "=r"(a) : "l"(p));
    return a;
}
__device__ __forceinline__ void cp_async16(uint32_t dst, const void* src) {
    asm volatile("cp.async.cg.shared.global [%0], [%1], 16;" :: "r"(dst), "l"(src));
}
__device__ __forceinline__ void cp_commit() { asm volatile("cp.async.commit_group;"); }
__device__ __forceinline__ void cp_wait1()  { asm volatile("cp.async.wait_group 1;"); }

__device__ __forceinline__ void ldsm_x4(uint32_t& r0, uint32_t& r1,
                                        uint32_t& r2, uint32_t& r3, uint32_t addr) {
    asm volatile("ldmatrix.sync.aligned.m8n8.x4.shared.b16 {%0,%1,%2,%3}, [%4];"
                 : "=r"(r0), "=r"(r1), "=r"(r2), "=r"(r3) : "r"(addr));
}
__device__ __forceinline__ void ldsm_x4_t(uint32_t& r0, uint32_t& r1,
                                          uint32_t& r2, uint32_t& r3, uint32_t addr) {
    asm volatile("ldmatrix.sync.aligned.m8n8.x4.trans.shared.b16 {%0,%1,%2,%3}, [%4];"
                 : "=r"(r0), "=r"(r1), "=r"(r2), "=r"(r3) : "r"(addr));
}
__device__ __forceinline__ void mma16816(float* c, const uint32_t* a, const uint32_t* b) {
    asm volatile("mma.sync.aligned.m16n8k16.row.col.f32.bf16.bf16.f32 "
                 "{%0,%1,%2,%3}, {%4,%5,%6,%7}, {%8,%9}, {%0,%1,%2,%3};"
                 : "+f"(c[0]), "+f"(c[1]), "+f"(c[2]), "+f"(c[3])
                 : "r"(a[0]), "r"(a[1]), "r"(a[2]), "r"(a[3]),
                   "r"(b[0]), "r"(b[1]));
}
__device__ __forceinline__ uint32_t packbf2(float lo, float hi) {
    __nv_bfloat162 v = __floats2bfloat162_rn(lo, hi);   // lo -> .x (low 16 bits)
    return *reinterpret_cast<uint32_t*>(&v);
}

// Swizzled byte offset of (row r, byte b within 128B row); XOR on 16B chunks.
#define SWZ(r, b) ((r) * 128 + ((b) ^ (((r) & 7) << 4)))

// ---------------------------------------------------------------------------
// Split conversions: fp32 -> bf16 [hi | lo | hi] along K (K = 1024)
// ---------------------------------------------------------------------------
__global__ void split_hi_lo_kernel(const float* __restrict__ in,
                                   __nv_bfloat16* __restrict__ out)
{
    int idx = blockIdx.x * blockDim.x + threadIdx.x;   // one float4 per thread
    int m  = idx >> 8;
    int c4 = idx & 255;
    float4 v = *(const float4*)(in + ((size_t)m << 10) + c4 * 4);
    float vv[4] = {v.x, v.y, v.z, v.w};
    __nv_bfloat16 h[4], l[4];
    #pragma unroll
    for (int i = 0; i < 4; ++i) {
        h[i] = __float2bfloat16(vv[i]);
        l[i] = __float2bfloat16(vv[i] - __bfloat162float(h[i]));
    }
    __nv_bfloat16* base = out + (size_t)m * KSPLIT + c4 * 4;
    *(__nv_bfloat162*)(base + 0)    = __halves2bfloat162(h[0], h[1]);
    *(__nv_bfloat162*)(base + 2)    = __halves2bfloat162(h[2], h[3]);
    *(__nv_bfloat162*)(base + 1024) = __halves2bfloat162(l[0], l[1]);
    *(__nv_bfloat162*)(base + 1026) = __halves2bfloat162(l[2], l[3]);
    *(__nv_bfloat162*)(base + 2048) = __halves2bfloat162(h[0], h[1]);
    *(__nv_bfloat162*)(base + 2050) = __halves2bfloat162(h[2], h[3]);
}

// W [K=1024, N] row-major -> B' [N, 3K] bf16: [hi | hi | lo]
__global__ void transpose_split_kernel(const float* __restrict__ W,
                                       __nv_bfloat16* __restrict__ out, int N)
{
    __shared__ float tile[32][33];
    const int n0 = blockIdx.x * 32, k0 = blockIdx.y * 32;
    const int tx = threadIdx.x, ty = threadIdx.y;   // (32, 8)
    #pragma unroll
    for (int i = 0; i < 4; ++i)
        tile[ty + i * 8][tx] = W[(size_t)(k0 + ty + i * 8) * N + n0 + tx];
    __syncthreads();
    #pragma unroll
    for (int i = 0; i < 4; ++i) {
        const int n = n0 + ty + i * 8;
        const int k = k0 + tx;
        const float v = tile[tx][ty + i * 8];
        const __nv_bfloat16 h = __float2bfloat16(v);
        const __nv_bfloat16 l = __float2bfloat16(v - __bfloat162float(h));
        __nv_bfloat16* row = out + (size_t)n * KSPLIT;
        row[k]               = h;
        row[D_MODEL + k]     = h;
        row[2 * D_MODEL + k] = l;
    }
}

// ---------------------------------------------------------------------------
// Tensor-core GEMM via mma.sync (HMMA), CTA 128x128, BK=64, 2-stage cp.async.
// MODE 0: C = A'B'^T + bias (fp32 out).
// MODE 1: qkv epilogue -> bf16 [3][B,H,S,64], q pre-scaled by 1/sqrt(HD).
// ---------------------------------------------------------------------------
#define BM 128
#define BN 128
#define BK 64
#define NCHUNK (KSPLIT / BK)                  // 48
#define STAGE_BYTES (BM * 128 + BN * 128)     // 32768
#define GEMM_SMEM (2 * STAGE_BYTES)           // 65536

template <int MODE>
__global__ __launch_bounds__(256)
void gemm_bf16_mma(const __nv_bfloat16* __restrict__ A,
                   const __nv_bfloat16* __restrict__ B,
                   const float* __restrict__ bias,
                   float* __restrict__ C,
                   __nv_bfloat16* __restrict__ qkvb,
                   int N)
{
    extern __shared__ char smem[];
    const uint32_t sb = smem_to_u32(smem);
    const int tid  = threadIdx.x;
    const int wid  = tid >> 5, lane = tid & 31;
    const int wm   = wid & 3;
    const int wn   = wid >> 2;
    const int m0   = blockIdx.y * BM;
    const int n0   = blockIdx.x * BN;

    const __nv_bfloat16* Ab = A + (size_t)m0 * KSPLIT;
    const __nv_bfloat16* Bb = B + (size_t)n0 * KSPLIT;

    auto load_stage = [&](int kc, int s) {
        const uint32_t ab = sb + s * STAGE_BYTES;
        const uint32_t bb = ab + BM * 128;
        const int koff = kc * BK;
        #pragma unroll
        for (int p = 0; p < 4; ++p) {
            const int idx = tid + p * 256;
            const int r = idx >> 3, q = idx & 7;
            cp_async16(ab + r * 128 + ((q ^ (r & 7)) << 4),
                       Ab + (size_t)r * KSPLIT + koff + q * 8);
        }
        #pragma unroll
        for (int p = 0; p < 4; ++p) {
            const int idx = tid + p * 256;
            const int r = idx >> 3, q = idx & 7;
            cp_async16(bb + r * 128 + ((q ^ (r & 7)) << 4),
                       Bb + (size_t)r * KSPLIT + koff + q * 8);
        }
    };

    float acc[2][8][4];
    #pragma unroll
    for (int mt = 0; mt < 2; ++mt)
        #pragma unroll
        for (int nt = 0; nt < 8; ++nt)
            #pragma unroll
            for (int i = 0; i < 4; ++i) acc[mt][nt][i] = 0.0f;

    load_stage(0, 0); cp_commit();
    load_stage(1, 1); cp_commit();

    for (int kc = 0; kc < NCHUNK; ++kc) {
        const int s = kc & 1;
        cp_wait1();
        __syncthreads();

        const uint32_t ab = sb + s * STAGE_BYTES;
        const uint32_t bb = ab + BM * 128;

        #pragma unroll
        for (int ks = 0; ks < 4; ++ks) {
            const int kb = ks * 32;

            uint32_t av[2][4];
            #pragma unroll
            for (int mt = 0; mt < 2; ++mt) {
                const int r  = wm * 32 + mt * 16 + (lane & 15);
                const int cb = kb + ((lane >> 4) << 4);
                ldsm_x4(av[mt][0], av[mt][1], av[mt][2], av[mt][3],
                        ab + SWZ(r, cb));
            }
            uint32_t bv[8][2];
            #pragma unroll
            for (int nt2 = 0; nt2 < 4; ++nt2) {
                const int r  = wn * 64 + nt2 * 16 + (lane & 7) + ((lane >> 4) << 3);
                const int cb = kb + (((lane >> 3) & 1) << 4);
                uint32_t t0, t1, t2, t3;
                ldsm_x4(t0, t1, t2, t3, bb + SWZ(r, cb));
                bv[nt2 * 2][0] = t0;  bv[nt2 * 2][1] = t1;
                bv[nt2 * 2 + 1][0] = t2;  bv[nt2 * 2 + 1][1] = t3;
            }
            #pragma unroll
            for (int mt = 0; mt < 2; ++mt)
                #pragma unroll
                for (int nt = 0; nt < 8; ++nt)
                    mma16816(acc[mt][nt], av[mt], bv[nt]);
        }

        __syncthreads();
        if (kc + 2 < NCHUNK) load_stage(kc + 2, s);
        cp_commit();
    }

    const int g  = lane >> 2;
    const int tg = lane & 3;
    #pragma unroll
    for (int mt = 0; mt < 2; ++mt) {
        const int row0 = m0 + wm * 32 + mt * 16 + g;
        #pragma unroll
        for (int nt = 0; nt < 8; ++nt) {
            const int col = n0 + wn * 64 + nt * 8 + tg * 2;
            const float2 bv = *(const float2*)(bias + col);
            float v0x = acc[mt][nt][0] + bv.x, v0y = acc[mt][nt][1] + bv.y;
            float v1x = acc[mt][nt][2] + bv.x, v1y = acc[mt][nt][3] + bv.y;
            if (MODE == 0) {
                *(float2*)(C + (size_t)row0 * N + col)       = make_float2(v0x, v0y);
                *(float2*)(C + (size_t)(row0 + 8) * N + col) = make_float2(v1x, v1y);
            } else {
                // qkv scatter: col -> section (q/k/v), head, dim
                const int sec = col >> 10;
                const int hh  = (col >> 6) & 15;
                const int dd  = col & 63;
                const float sc = (sec == 0) ? 0.125f : 1.0f;   // fold 1/sqrt(64) into q
                __nv_bfloat16* dst = qkvb + (size_t)sec * QKV_E;
                const size_t i0 = ((size_t)((row0 >> 11) * H_HEADS + hh) * S_SEQ
                                   + (row0 & 2047)) * HD + dd;
                const size_t i1 = ((size_t)(((row0 + 8) >> 11) * H_HEADS + hh) * S_SEQ
                                   + ((row0 + 8) & 2047)) * HD + dd;
                *(uint32_t*)(dst + i0) = packbf2(v0x * sc, v0y * sc);
                *(uint32_t*)(dst + i1) = packbf2(v1x * sc, v1y * sc);
            }
        }
    }
}

// ---------------------------------------------------------------------------
// Flash attention on tensor cores (mma.sync bf16, fp32 accum).
// CTA: 128 threads (4 warps), 64 q-rows; warp w owns rows w*16..w*16+15.
// Bc = 64 keys/iter, 32 iters; K/V double-buffered via cp.async.
// P fragments built register-to-register from S accumulators.
// ---------------------------------------------------------------------------
#define AQ 64
#define AK 64
#define AIT (S_SEQ / AK)          // 32
// smem: Q 8KB | K[2] 8KB each | V[2] 8KB each = 40 KB static
#define SM_Q 0
#define SM_K 8192
#define SM_V 24576

__global__ __launch_bounds__(128)
void flash_attn_bf16(const __nv_bfloat16* __restrict__ qkvb,
                     float* __restrict__ out)
{
    __shared__ __align__(1024) char sm[5 * 8192];
    const uint32_t sb = smem_to_u32(sm);
    const int tid = threadIdx.x, w = tid >> 5, lane = tid & 31;
    const int qt = blockIdx.x, h = blockIdx.y, b = blockIdx.z;

    const __nv_bfloat16* qb = qkvb + ((size_t)(b * H_HEADS + h) * S_SEQ) * HD;
    const __nv_bfloat16* kb = qb + QKV_E;
    const __nv_bfloat16* vb = qb + 2 * (size_t)QKV_E;

    // Q tile: 64 rows x 128B (q already scaled by 1/sqrt(HD))
    #pragma unroll
    for (int p = 0; p < 4; ++p) {
        const int idx = tid + p * 128;
        const int r = idx >> 3, q = idx & 7;
        cp_async16(sb + SM_Q + r * 128 + ((q ^ (r & 7)) << 4),
                   qb + (size_t)(qt * AQ + r) * HD + q * 8);
    }

    auto load_kv = [&](int t, int s) {
        const __nv_bfloat16* ksrc = kb + (size_t)t * AK * HD;
        const __nv_bfloat16* vsrc = vb + (size_t)t * AK * HD;
        #pragma unroll
        for (int p = 0; p < 4; ++p) {
            const int idx = tid + p * 128;
            const int r = idx >> 3, q = idx & 7;
            const uint32_t off = r * 128 + ((q ^ (r & 7)) << 4);
            cp_async16(sb + SM_K + s * 8192 + off, ksrc + (size_t)r * HD + q * 8);
            cp_async16(sb + SM_V + s * 8192 + off, vsrc + (size_t)r * HD + q * 8);
        }
    };

    load_kv(0, 0); cp_commit();          // group0: Q + KV0
    load_kv(1, 1); cp_commit();          // group1: KV1
    cp_wait1();                          // group0 done
    __syncthreads();

    // Q fragments (persist across the whole loop)
    uint32_t qf[4][4];
    #pragma unroll
    for (int ks = 0; ks < 4; ++ks) {
        const int r  = w * 16 + (lane & 15);
        const int cb = ks * 32 + ((lane >> 4) << 4);
        ldsm_x4(qf[ks][0], qf[ks][1], qf[ks][2], qf[ks][3], sb + SM_Q + SWZ(r, cb));
    }

    float m2[2] = {-1e30f, -1e30f}, l2[2] = {0.0f, 0.0f};
    float oacc[8][4];
    #pragma unroll
    for (int nt = 0; nt < 8; ++nt)
        #pragma unroll
        for (int i = 0; i < 4; ++i) oacc[nt][i] = 0.0f;

    for (int t = 0; t < AIT; ++t) {
        const int s = t & 1;
        if (t > 0) { cp_wait1(); __syncthreads(); }

        // ---- S = Q K^T (per warp: 16 rows x 64 keys) ----
        float sacc[8][4];
        #pragma unroll
        for (int nt = 0; nt < 8; ++nt)
            #pragma unroll
            for (int i = 0; i < 4; ++i) sacc[nt][i] = 0.0f;

        const uint32_t kbuf = sb + SM_K + s * 8192;
        #pragma unroll
        for (int ks = 0; ks < 4; ++ks) {
            uint32_t bv[8][2];
            #pragma unroll
            for (int nt2 = 0; nt2 < 4; ++nt2) {
                const int r  = nt2 * 16 + (lane & 7) + ((lane >> 4) << 3);
                const int cb = ks * 32 + (((lane >> 3) & 1) << 4);
                uint32_t t0, t1, t2, t3;
                ldsm_x4(t0, t1, t2, t3, kbuf + SWZ(r, cb));
                bv[nt2 * 2][0] = t0;  bv[nt2 * 2][1] = t1;
                bv[nt2 * 2 + 1][0] = t2;  bv[nt2 * 2 + 1][1] = t3;
            }
            #pragma unroll
            for (int nt = 0; nt < 8; ++nt)
                mma16816(sacc[nt], qf[ks], bv[nt]);
        }

        // ---- online softmax (rows g and g+8; stats shared across quad) ----
        #pragma unroll
        for (int hf = 0; hf < 2; ++hf) {
            float tmax = -1e30f;
            #pragma unroll
            for (int nt = 0; nt < 8; ++nt)
                tmax = fmaxf(tmax, fmaxf(sacc[nt][2 * hf], sacc[nt][2 * hf + 1]));
            tmax = fmaxf(tmax, __shfl_xor_sync(0xffffffffu, tmax, 1));
            tmax = fmaxf(tmax, __shfl_xor_sync(0xffffffffu, tmax, 2));

            const float mn    = fmaxf(m2[hf], tmax);
            const float alpha = __expf(m2[hf] - mn);
            m2[hf] = mn;

            float rs = 0.0f;
            #pragma unroll
            for (int nt = 0; nt < 8; ++nt) {
                const float p0 = __expf(sacc[nt][2 * hf]     - mn);
                const float p1 = __expf(sacc[nt][2 * hf + 1] - mn);
                sacc[nt][2 * hf] = p0;  sacc[nt][2 * hf + 1] = p1;
                rs += p0 + p1;
            }
            rs += __shfl_xor_sync(0xffffffffu, rs, 1);
            rs += __shfl_xor_sync(0xffffffffu, rs, 2);
            l2[hf] = l2[hf] * alpha + rs;

            #pragma unroll
            for (int nt = 0; nt < 8; ++nt) {
                oacc[nt][2 * hf]     *= alpha;
                oacc[nt][2 * hf + 1] *= alpha;
            }
        }

        // ---- P fragments from S accumulators (registers only) ----
        uint32_t pf[4][4];
        #pragma unroll
        for (int c = 0; c < 4; ++c) {
            pf[c][0] = packbf2(sacc[2 * c][0],     sacc[2 * c][1]);
            pf[c][1] = packbf2(sacc[2 * c][2],     sacc[2 * c][3]);
            pf[c][2] = packbf2(sacc[2 * c + 1][0], sacc[2 * c + 1][1]);
            pf[c][3] = packbf2(sacc[2 * c + 1][2], sacc[2 * c + 1][3]);
        }

        // ---- O += P V  (V via ldmatrix.trans; dims are the n-axis) ----
        const uint32_t vbuf = sb + SM_V + s * 8192;
        #pragma unroll
        for (int ks = 0; ks < 4; ++ks) {
            uint32_t vv[8][2];
            #pragma unroll
            for (int ng = 0; ng < 4; ++ng) {
                const int r  = ks * 16 + (lane & 15);
                const int cb = ng * 32 + ((lane >> 4) << 4);
                uint32_t t0, t1, t2, t3;
                ldsm_x4_t(t0, t1, t2, t3, vbuf + SWZ(r, cb));
                vv[ng * 2][0] = t0;  vv[ng * 2][1] = t1;
                vv[ng * 2 + 1][0] = t2;  vv[ng * 2 + 1][1] = t3;
            }
            #pragma unroll
            for (int nt = 0; nt < 8; ++nt)
                mma16816(oacc[nt], pf[ks], vv[nt]);
        }

        __syncthreads();
        if (t + 2 < AIT) load_kv(t + 2, s);
        cp_commit();
    }

    // ---- epilogue: normalize, write fp32 [B*S, D] at col h*64+d ----
    const int g  = lane >> 2;
    const int tg = lane & 3;
    const float inv0 = __fdividef(1.0f, l2[0]);
    const float inv1 = __fdividef(1.0f, l2[1]);
    const int row0 = b * S_SEQ + qt * AQ + w * 16 + g;
    #pragma unroll
    for (int nt = 0; nt < 8; ++nt) {
        const int col = h * HD + nt * 8 + tg * 2;
        *(float2*)(out + (size_t)row0 * D_MODEL + col) =
            make_float2(oacc[nt][0] * inv0, oacc[nt][1] * inv0);
        *(float2*)(out + (size_t)(row0 + 8) * D_MODEL + col) =
            make_float2(oacc[nt][2] * inv1, oacc[nt][3] * inv1);
    }
}

// ---------------------------------------------------------------------------
// Launch
// ---------------------------------------------------------------------------
extern "C" void kernel_launch(void* const* d_in, const int* in_sizes, int n_in,
                              void* d_out, int out_size)
{
    const float* x     = (const float*)d_in[0];
    const float* W_qkv = (const float*)d_in[1];
    const float* b_qkv = (const float*)d_in[2];
    const float* W_out = (const float*)d_in[3];
    const float* b_out = (const float*)d_in[4];
    float* out = (float*)d_out;

    float* attn_s;
    __nv_bfloat16 *Abf, *Bqkv, *Bout, *qkvb;
    cudaGetSymbolAddress((void**)&attn_s, g_attn);
    cudaGetSymbolAddress((void**)&Abf,    g_Abf);
    cudaGetSymbolAddress((void**)&Bqkv,   g_Bqkv);
    cudaGetSymbolAddress((void**)&Bout,   g_Bout);
    cudaGetSymbolAddress((void**)&qkvb,   g_qkvb);

    cudaFuncSetAttribute(gemm_bf16_mma<0>,
                         cudaFuncAttributeMaxDynamicSharedMemorySize, GEMM_SMEM);
    cudaFuncSetAttribute(gemm_bf16_mma<1>,
                         cudaFuncAttributeMaxDynamicSharedMemorySize, GEMM_SMEM);

    // 1) split/convert inputs
    split_hi_lo_kernel<<<M_ROWS, 256>>>(x, Abf);
    transpose_split_kernel<<<dim3(QKV_N / 32, D_MODEL / 32), dim3(32, 8)>>>(W_qkv, Bqkv, QKV_N);
    transpose_split_kernel<<<dim3(D_MODEL / 32, D_MODEL / 32), dim3(32, 8)>>>(W_out, Bout, D_MODEL);

    // 2) QKV projection (HMMA) -> bf16 q|k|v in [B,H,S,64], q pre-scaled
    gemm_bf16_mma<1><<<dim3(QKV_N / BN, M_ROWS / BM), 256, GEMM_SMEM>>>(
        Abf, Bqkv, b_qkv, nullptr, qkvb, QKV_N);

    // 3) Flash attention on tensor cores -> fp32 g_attn
    flash_attn_bf16<<<dim3(S_SEQ / AQ, H_HEADS, B_BATCH), 128>>>(qkvb, attn_s);

    // 4) split attn output, then output projection (HMMA) -> out
    split_hi_lo_kernel<<<M_ROWS, 256>>>(attn_s, Abf);
    gemm_bf16_mma<0><<<dim3(D_MODEL / BN, M_ROWS / BM), 256, GEMM_SMEM>>>(
        Abf, Bout, b_out, out, nullptr, D_MODEL);
}

// round 9
// speedup vs baseline: 4.7040x; 1.0872x over previous
#include <cuda_runtime.h>
#include <cuda_bf16.h>
#include <math.h>
#include <stdint.h>

// ---------------------------------------------------------------------------
// Problem constants
// ---------------------------------------------------------------------------
#define D_MODEL 1024
#define H_HEADS 16
#define HD      64
#define B_BATCH 2
#define S_SEQ   2048
#define M_ROWS  (B_BATCH * S_SEQ)      // 4096
#define QKV_N   (3 * D_MODEL)          // 3072
#define KSPLIT  (3 * D_MODEL)          // split-K: [hi | lo | hi] of K=1024
#define QKV_E   (B_BATCH * H_HEADS * S_SEQ * HD)   // 4,194,304 per q/k/v

// ---------------------------------------------------------------------------
// Scratch (device globals — allocation-free)
// ---------------------------------------------------------------------------
__device__ __align__(256) __nv_bfloat16 g_Abf [M_ROWS * KSPLIT];    // A' split
__device__ __align__(256) __nv_bfloat16 g_Bqkv[QKV_N  * KSPLIT];    // W_qkv^T split
__device__ __align__(256) __nv_bfloat16 g_Bout[D_MODEL * KSPLIT];   // W_out^T split
__device__ __align__(256) __nv_bfloat16 g_qkvb[3 * QKV_E];          // bf16 q|k|v [B,H,S,64]

// ---------------------------------------------------------------------------
// Helpers (portable PTX only: ldmatrix / mma.sync / cp.async — no tcgen05)
// ---------------------------------------------------------------------------
__device__ __forceinline__ uint32_t smem_to_u32(const void* p) {
    uint32_t a;
    asm("{ .reg .u64 t; cvta.to.shared.u64 t, %1; cvt.u32.u64 %0, t; }"
        : "=r"(a) : "l"(p));
    return a;
}
__device__ __forceinline__ void cp_async16(uint32_t dst, const void* src) {
    asm volatile("cp.async.cg.shared.global [%0], [%1], 16;" :: "r"(dst), "l"(src));
}
__device__ __forceinline__ void cp_commit() { asm volatile("cp.async.commit_group;"); }
__device__ __forceinline__ void cp_wait1()  { asm volatile("cp.async.wait_group 1;"); }

__device__ __forceinline__ void ldsm_x4(uint32_t& r0, uint32_t& r1,
                                        uint32_t& r2, uint32_t& r3, uint32_t addr) {
    asm volatile("ldmatrix.sync.aligned.m8n8.x4.shared.b16 {%0,%1,%2,%3}, [%4];"
                 : "=r"(r0), "=r"(r1), "=r"(r2), "=r"(r3) : "r"(addr));
}
__device__ __forceinline__ void ldsm_x4_t(uint32_t& r0, uint32_t& r1,
                                          uint32_t& r2, uint32_t& r3, uint32_t addr) {
    asm volatile("ldmatrix.sync.aligned.m8n8.x4.trans.shared.b16 {%0,%1,%2,%3}, [%4];"
                 : "=r"(r0), "=r"(r1), "=r"(r2), "=r"(r3) : "r"(addr));
}
__device__ __forceinline__ void mma16816(float* c, const uint32_t* a, const uint32_t* b) {
    asm volatile("mma.sync.aligned.m16n8k16.row.col.f32.bf16.bf16.f32 "
                 "{%0,%1,%2,%3}, {%4,%5,%6,%7}, {%8,%9}, {%0,%1,%2,%3};"
                 : "+f"(c[0]), "+f"(c[1]), "+f"(c[2]), "+f"(c[3])
                 : "r"(a[0]), "r"(a[1]), "r"(a[2]), "r"(a[3]),
                   "r"(b[0]), "r"(b[1]));
}
__device__ __forceinline__ uint32_t packbf2(float lo, float hi) {
    __nv_bfloat162 v = __floats2bfloat162_rn(lo, hi);   // lo -> .x (low 16 bits)
    return *reinterpret_cast<uint32_t*>(&v);
}

// Swizzled byte offset of (row r, byte b within 128B row); XOR on 16B chunks.
#define SWZ(r, b) ((r) * 128 + ((b) ^ (((r) & 7) << 4)))

// ---------------------------------------------------------------------------
// Split conversions: fp32 -> bf16 [hi | lo | hi] along K (K = 1024)
// ---------------------------------------------------------------------------
__global__ void split_hi_lo_kernel(const float* __restrict__ in,
                                   __nv_bfloat16* __restrict__ out)
{
    int idx = blockIdx.x * blockDim.x + threadIdx.x;   // one float4 per thread
    int m  = idx >> 8;
    int c4 = idx & 255;
    float4 v = *(const float4*)(in + ((size_t)m << 10) + c4 * 4);
    float vv[4] = {v.x, v.y, v.z, v.w};
    __nv_bfloat16 h[4], l[4];
    #pragma unroll
    for (int i = 0; i < 4; ++i) {
        h[i] = __float2bfloat16(vv[i]);
        l[i] = __float2bfloat16(vv[i] - __bfloat162float(h[i]));
    }
    __nv_bfloat16* base = out + (size_t)m * KSPLIT + c4 * 4;
    *(__nv_bfloat162*)(base + 0)    = __halves2bfloat162(h[0], h[1]);
    *(__nv_bfloat162*)(base + 2)    = __halves2bfloat162(h[2], h[3]);
    *(__nv_bfloat162*)(base + 1024) = __halves2bfloat162(l[0], l[1]);
    *(__nv_bfloat162*)(base + 1026) = __halves2bfloat162(l[2], l[3]);
    *(__nv_bfloat162*)(base + 2048) = __halves2bfloat162(h[0], h[1]);
    *(__nv_bfloat162*)(base + 2050) = __halves2bfloat162(h[2], h[3]);
}

// W [K=1024, N] row-major -> B' [N, 3K] bf16: [hi | hi | lo]
__global__ void transpose_split_kernel(const float* __restrict__ W,
                                       __nv_bfloat16* __restrict__ out, int N)
{
    __shared__ float tile[32][33];
    const int n0 = blockIdx.x * 32, k0 = blockIdx.y * 32;
    const int tx = threadIdx.x, ty = threadIdx.y;   // (32, 8)
    #pragma unroll
    for (int i = 0; i < 4; ++i)
        tile[ty + i * 8][tx] = W[(size_t)(k0 + ty + i * 8) * N + n0 + tx];
    __syncthreads();
    #pragma unroll
    for (int i = 0; i < 4; ++i) {
        const int n = n0 + ty + i * 8;
        const int k = k0 + tx;
        const float v = tile[tx][ty + i * 8];
        const __nv_bfloat16 h = __float2bfloat16(v);
        const __nv_bfloat16 l = __float2bfloat16(v - __bfloat162float(h));
        __nv_bfloat16* row = out + (size_t)n * KSPLIT;
        row[k]               = h;
        row[D_MODEL + k]     = h;
        row[2 * D_MODEL + k] = l;
    }
}

// ---------------------------------------------------------------------------
// Tensor-core GEMM via mma.sync (HMMA), CTA 128x128, BK=64.
// 3-stage cp.async pipeline, ONE __syncthreads per chunk:
//   barrier at iter k guarantees all warps finished reading stage (k-1)%3,
//   which is exactly the buffer refilled (for chunk k+2) at iter k.
// MODE 0: C = A'B'^T + bias (fp32 out).
// MODE 1: qkv epilogue -> bf16 [3][B,H,S,64], q pre-scaled by 1/sqrt(HD).
// ---------------------------------------------------------------------------
#define BM 128
#define BN 128
#define BK 64
#define NCHUNK (KSPLIT / BK)                  // 48
#define STAGE_BYTES (BM * 128 + BN * 128)     // 32768
#define NSTAGE 3
#define GEMM_SMEM (NSTAGE * STAGE_BYTES)      // 98304

template <int MODE>
__global__ __launch_bounds__(256, 2)
void gemm_bf16_mma(const __nv_bfloat16* __restrict__ A,
                   const __nv_bfloat16* __restrict__ B,
                   const float* __restrict__ bias,
                   float* __restrict__ C,
                   __nv_bfloat16* __restrict__ qkvb,
                   int N)
{
    extern __shared__ char smem[];
    const uint32_t sb = smem_to_u32(smem);
    const int tid  = threadIdx.x;
    const int wid  = tid >> 5, lane = tid & 31;
    const int wm   = wid & 3;
    const int wn   = wid >> 2;
    const int m0   = blockIdx.y * BM;
    const int n0   = blockIdx.x * BN;

    const __nv_bfloat16* Ab = A + (size_t)m0 * KSPLIT;
    const __nv_bfloat16* Bb = B + (size_t)n0 * KSPLIT;

    auto load_stage = [&](int kc, int s) {
        const uint32_t ab = sb + s * STAGE_BYTES;
        const uint32_t bb = ab + BM * 128;
        const int koff = kc * BK;
        #pragma unroll
        for (int p = 0; p < 4; ++p) {
            const int idx = tid + p * 256;
            const int r = idx >> 3, q = idx & 7;
            cp_async16(ab + r * 128 + ((q ^ (r & 7)) << 4),
                       Ab + (size_t)r * KSPLIT + koff + q * 8);
        }
        #pragma unroll
        for (int p = 0; p < 4; ++p) {
            const int idx = tid + p * 256;
            const int r = idx >> 3, q = idx & 7;
            cp_async16(bb + r * 128 + ((q ^ (r & 7)) << 4),
                       Bb + (size_t)r * KSPLIT + koff + q * 8);
        }
    };

    float acc[2][8][4];
    #pragma unroll
    for (int mt = 0; mt < 2; ++mt)
        #pragma unroll
        for (int nt = 0; nt < 8; ++nt)
            #pragma unroll
            for (int i = 0; i < 4; ++i) acc[mt][nt][i] = 0.0f;

    load_stage(0, 0); cp_commit();
    load_stage(1, 1); cp_commit();

    int s = 0, ls = 2;                       // consume stage, load stage
    for (int kc = 0; kc < NCHUNK; ++kc) {
        cp_wait1();
        __syncthreads();                     // stage s ready; stage ls reads done

        const uint32_t ab = sb + s * STAGE_BYTES;
        const uint32_t bb = ab + BM * 128;

        #pragma unroll
        for (int ks = 0; ks < 4; ++ks) {
            const int kb = ks * 32;

            uint32_t av[2][4];
            #pragma unroll
            for (int mt = 0; mt < 2; ++mt) {
                const int r  = wm * 32 + mt * 16 + (lane & 15);
                const int cb = kb + ((lane >> 4) << 4);
                ldsm_x4(av[mt][0], av[mt][1], av[mt][2], av[mt][3],
                        ab + SWZ(r, cb));
            }
            uint32_t bv[8][2];
            #pragma unroll
            for (int nt2 = 0; nt2 < 4; ++nt2) {
                const int r  = wn * 64 + nt2 * 16 + (lane & 7) + ((lane >> 4) << 3);
                const int cb = kb + (((lane >> 3) & 1) << 4);
                uint32_t t0, t1, t2, t3;
                ldsm_x4(t0, t1, t2, t3, bb + SWZ(r, cb));
                bv[nt2 * 2][0] = t0;  bv[nt2 * 2][1] = t1;
                bv[nt2 * 2 + 1][0] = t2;  bv[nt2 * 2 + 1][1] = t3;
            }
            #pragma unroll
            for (int mt = 0; mt < 2; ++mt)
                #pragma unroll
                for (int nt = 0; nt < 8; ++nt)
                    mma16816(acc[mt][nt], av[mt], bv[nt]);
        }

        if (kc + 2 < NCHUNK) load_stage(kc + 2, ls);
        cp_commit();
        s  = (s  == NSTAGE - 1) ? 0 : s + 1;
        ls = (ls == NSTAGE - 1) ? 0 : ls + 1;
    }

    const int g  = lane >> 2;
    const int tg = lane & 3;
    #pragma unroll
    for (int mt = 0; mt < 2; ++mt) {
        const int row0 = m0 + wm * 32 + mt * 16 + g;
        #pragma unroll
        for (int nt = 0; nt < 8; ++nt) {
            const int col = n0 + wn * 64 + nt * 8 + tg * 2;
            const float2 bv = *(const float2*)(bias + col);
            float v0x = acc[mt][nt][0] + bv.x, v0y = acc[mt][nt][1] + bv.y;
            float v1x = acc[mt][nt][2] + bv.x, v1y = acc[mt][nt][3] + bv.y;
            if (MODE == 0) {
                *(float2*)(C + (size_t)row0 * N + col)       = make_float2(v0x, v0y);
                *(float2*)(C + (size_t)(row0 + 8) * N + col) = make_float2(v1x, v1y);
            } else {
                const int sec = col >> 10;
                const int hh  = (col >> 6) & 15;
                const int dd  = col & 63;
                const float sc = (sec == 0) ? 0.125f : 1.0f;
                __nv_bfloat16* dst = qkvb + (size_t)sec * QKV_E;
                const size_t i0 = ((size_t)((row0 >> 11) * H_HEADS + hh) * S_SEQ
                                   + (row0 & 2047)) * HD + dd;
                const size_t i1 = ((size_t)(((row0 + 8) >> 11) * H_HEADS + hh) * S_SEQ
                                   + ((row0 + 8) & 2047)) * HD + dd;
                *(uint32_t*)(dst + i0) = packbf2(v0x * sc, v0y * sc);
                *(uint32_t*)(dst + i1) = packbf2(v1x * sc, v1y * sc);
            }
        }
    }
}

// ---------------------------------------------------------------------------
// Flash attention on tensor cores (mma.sync bf16, fp32 accum).
// 128 threads, 64 q-rows/CTA, Bc=64; 3-stage cp.async K/V, one sync per tile.
// Epilogue writes the hi/lo/hi bf16 A' rows directly (fused split).
// ---------------------------------------------------------------------------
#define AQ 64
#define AK 64
#define AIT (S_SEQ / AK)          // 32
// dynamic smem: Q 8KB | K[3] 8KB each | V[3] 8KB each = 56 KB
#define SM_Q 0
#define SM_K 8192
#define SM_V (8192 + 3 * 8192)
#define ATT_SMEM (SM_V + 3 * 8192)   // 57344

__global__ __launch_bounds__(128)
void flash_attn_bf16(const __nv_bfloat16* __restrict__ qkvb,
                     __nv_bfloat16* __restrict__ Aout)
{
    extern __shared__ char sm[];
    const uint32_t sb = smem_to_u32(sm);
    const int tid = threadIdx.x, w = tid >> 5, lane = tid & 31;
    const int qt = blockIdx.x, h = blockIdx.y, b = blockIdx.z;

    const __nv_bfloat16* qb = qkvb + ((size_t)(b * H_HEADS + h) * S_SEQ) * HD;
    const __nv_bfloat16* kb = qb + QKV_E;
    const __nv_bfloat16* vb = qb + 2 * (size_t)QKV_E;

    auto load_kv = [&](int t, int s) {
        const __nv_bfloat16* ksrc = kb + (size_t)t * AK * HD;
        const __nv_bfloat16* vsrc = vb + (size_t)t * AK * HD;
        #pragma unroll
        for (int p = 0; p < 4; ++p) {
            const int idx = tid + p * 128;
            const int r = idx >> 3, q = idx & 7;
            const uint32_t off = r * 128 + ((q ^ (r & 7)) << 4);
            cp_async16(sb + SM_K + s * 8192 + off, ksrc + (size_t)r * HD + q * 8);
            cp_async16(sb + SM_V + s * 8192 + off, vsrc + (size_t)r * HD + q * 8);
        }
    };

    // group0: Q + KV0 ; group1: KV1
    #pragma unroll
    for (int p = 0; p < 4; ++p) {
        const int idx = tid + p * 128;
        const int r = idx >> 3, q = idx & 7;
        cp_async16(sb + SM_Q + r * 128 + ((q ^ (r & 7)) << 4),
                   qb + (size_t)(qt * AQ + r) * HD + q * 8);
    }
    load_kv(0, 0); cp_commit();
    load_kv(1, 1); cp_commit();
    cp_wait1();
    __syncthreads();

    // Q fragments (persist)
    uint32_t qf[4][4];
    #pragma unroll
    for (int ks = 0; ks < 4; ++ks) {
        const int r  = w * 16 + (lane & 15);
        const int cb = ks * 32 + ((lane >> 4) << 4);
        ldsm_x4(qf[ks][0], qf[ks][1], qf[ks][2], qf[ks][3], sb + SM_Q + SWZ(r, cb));
    }

    float m2[2] = {-1e30f, -1e30f}, l2[2] = {0.0f, 0.0f};
    float oacc[8][4];
    #pragma unroll
    for (int nt = 0; nt < 8; ++nt)
        #pragma unroll
        for (int i = 0; i < 4; ++i) oacc[nt][i] = 0.0f;

    int s = 0, ls = 2;
    for (int t = 0; t < AIT; ++t) {
        if (t > 0) { cp_wait1(); __syncthreads(); }

        // ---- S = Q K^T ----
        float sacc[8][4];
        #pragma unroll
        for (int nt = 0; nt < 8; ++nt)
            #pragma unroll
            for (int i = 0; i < 4; ++i) sacc[nt][i] = 0.0f;

        const uint32_t kbuf = sb + SM_K + s * 8192;
        #pragma unroll
        for (int ks = 0; ks < 4; ++ks) {
            uint32_t bv[8][2];
            #pragma unroll
            for (int nt2 = 0; nt2 < 4; ++nt2) {
                const int r  = nt2 * 16 + (lane & 7) + ((lane >> 4) << 3);
                const int cb = ks * 32 + (((lane >> 3) & 1) << 4);
                uint32_t t0, t1, t2, t3;
                ldsm_x4(t0, t1, t2, t3, kbuf + SWZ(r, cb));
                bv[nt2 * 2][0] = t0;  bv[nt2 * 2][1] = t1;
                bv[nt2 * 2 + 1][0] = t2;  bv[nt2 * 2 + 1][1] = t3;
            }
            #pragma unroll
            for (int nt = 0; nt < 8; ++nt)
                mma16816(sacc[nt], qf[ks], bv[nt]);
        }

        // ---- online softmax ----
        #pragma unroll
        for (int hf = 0; hf < 2; ++hf) {
            float tmax = -1e30f;
            #pragma unroll
            for (int nt = 0; nt < 8; ++nt)
                tmax = fmaxf(tmax, fmaxf(sacc[nt][2 * hf], sacc[nt][2 * hf + 1]));
            tmax = fmaxf(tmax, __shfl_xor_sync(0xffffffffu, tmax, 1));
            tmax = fmaxf(tmax, __shfl_xor_sync(0xffffffffu, tmax, 2));

            const float mn    = fmaxf(m2[hf], tmax);
            const float alpha = __expf(m2[hf] - mn);
            m2[hf] = mn;

            float rs = 0.0f;
            #pragma unroll
            for (int nt = 0; nt < 8; ++nt) {
                const float p0 = __expf(sacc[nt][2 * hf]     - mn);
                const float p1 = __expf(sacc[nt][2 * hf + 1] - mn);
                sacc[nt][2 * hf] = p0;  sacc[nt][2 * hf + 1] = p1;
                rs += p0 + p1;
            }
            rs += __shfl_xor_sync(0xffffffffu, rs, 1);
            rs += __shfl_xor_sync(0xffffffffu, rs, 2);
            l2[hf] = l2[hf] * alpha + rs;

            #pragma unroll
            for (int nt = 0; nt < 8; ++nt) {
                oacc[nt][2 * hf]     *= alpha;
                oacc[nt][2 * hf + 1] *= alpha;
            }
        }

        // ---- P fragments (registers only) ----
        uint32_t pf[4][4];
        #pragma unroll
        for (int c = 0; c < 4; ++c) {
            pf[c][0] = packbf2(sacc[2 * c][0],     sacc[2 * c][1]);
            pf[c][1] = packbf2(sacc[2 * c][2],     sacc[2 * c][3]);
            pf[c][2] = packbf2(sacc[2 * c + 1][0], sacc[2 * c + 1][1]);
            pf[c][3] = packbf2(sacc[2 * c + 1][2], sacc[2 * c + 1][3]);
        }

        // ---- O += P V ----
        const uint32_t vbuf = sb + SM_V + s * 8192;
        #pragma unroll
        for (int ks = 0; ks < 4; ++ks) {
            uint32_t vv[8][2];
            #pragma unroll
            for (int ng = 0; ng < 4; ++ng) {
                const int r  = ks * 16 + (lane & 15);
                const int cb = ng * 32 + ((lane >> 4) << 4);
                uint32_t t0, t1, t2, t3;
                ldsm_x4_t(t0, t1, t2, t3, vbuf + SWZ(r, cb));
                vv[ng * 2][0] = t0;  vv[ng * 2][1] = t1;
                vv[ng * 2 + 1][0] = t2;  vv[ng * 2 + 1][1] = t3;
            }
            #pragma unroll
            for (int nt = 0; nt < 8; ++nt)
                mma16816(oacc[nt], pf[ks], vv[nt]);
        }

        if (t + 2 < AIT) load_kv(t + 2, ls);
        cp_commit();
        s  = (s  == 2) ? 0 : s + 1;
        ls = (ls == 2) ? 0 : ls + 1;
    }

    // ---- epilogue: normalize + fused hi/lo/hi split into A' ----
    const int g  = lane >> 2;
    const int tg = lane & 3;
    const float inv0 = __fdividef(1.0f, l2[0]);
    const float inv1 = __fdividef(1.0f, l2[1]);
    const int row0 = b * S_SEQ + qt * AQ + w * 16 + g;
    #pragma unroll
    for (int nt = 0; nt < 8; ++nt) {
        const int col = h * HD + nt * 8 + tg * 2;
        #pragma unroll
        for (int rr = 0; rr < 2; ++rr) {
            const float inv = rr ? inv1 : inv0;
            const float vx = oacc[nt][2 * rr]     * inv;
            const float vy = oacc[nt][2 * rr + 1] * inv;
            const __nv_bfloat16 hx = __float2bfloat16(vx);
            const __nv_bfloat16 hy = __float2bfloat16(vy);
            const __nv_bfloat16 lx = __float2bfloat16(vx - __bfloat162float(hx));
            const __nv_bfloat16 ly = __float2bfloat16(vy - __bfloat162float(hy));
            __nv_bfloat16* dst = Aout + (size_t)(row0 + rr * 8) * KSPLIT + col;
            const uint32_t hp = *(const uint32_t*)&hx | ((uint32_t)*(const uint16_t*)&hy << 16);
            const uint32_t lp = *(const uint32_t*)&lx | ((uint32_t)*(const uint16_t*)&ly << 16);
            *(uint32_t*)(dst)            = hp;
            *(uint32_t*)(dst + D_MODEL)  = lp;
            *(uint32_t*)(dst + 2 * D_MODEL) = hp;
        }
    }
}

// ---------------------------------------------------------------------------
// Launch
// ---------------------------------------------------------------------------
extern "C" void kernel_launch(void* const* d_in, const int* in_sizes, int n_in,
                              void* d_out, int out_size)
{
    const float* x     = (const float*)d_in[0];
    const float* W_qkv = (const float*)d_in[1];
    const float* b_qkv = (const float*)d_in[2];
    const float* W_out = (const float*)d_in[3];
    const float* b_out = (const float*)d_in[4];
    float* out = (float*)d_out;

    __nv_bfloat16 *Abf, *Bqkv, *Bout, *qkvb;
    cudaGetSymbolAddress((void**)&Abf,  g_Abf);
    cudaGetSymbolAddress((void**)&Bqkv, g_Bqkv);
    cudaGetSymbolAddress((void**)&Bout, g_Bout);
    cudaGetSymbolAddress((void**)&qkvb, g_qkvb);

    cudaFuncSetAttribute(gemm_bf16_mma<0>,
                         cudaFuncAttributeMaxDynamicSharedMemorySize, GEMM_SMEM);
    cudaFuncSetAttribute(gemm_bf16_mma<1>,
                         cudaFuncAttributeMaxDynamicSharedMemorySize, GEMM_SMEM);
    cudaFuncSetAttribute(flash_attn_bf16,
                         cudaFuncAttributeMaxDynamicSharedMemorySize, ATT_SMEM);

    // 1) split/convert inputs
    split_hi_lo_kernel<<<M_ROWS, 256>>>(x, Abf);
    transpose_split_kernel<<<dim3(QKV_N / 32, D_MODEL / 32), dim3(32, 8)>>>(W_qkv, Bqkv, QKV_N);
    transpose_split_kernel<<<dim3(D_MODEL / 32, D_MODEL / 32), dim3(32, 8)>>>(W_out, Bout, D_MODEL);

    // 2) QKV projection (HMMA, 3-stage) -> bf16 q|k|v [B,H,S,64], q pre-scaled
    gemm_bf16_mma<1><<<dim3(QKV_N / BN, M_ROWS / BM), 256, GEMM_SMEM>>>(
        Abf, Bqkv, b_qkv, nullptr, qkvb, QKV_N);

    // 3) Flash attention (HMMA, 3-stage) -> fused hi/lo split into A'
    flash_attn_bf16<<<dim3(S_SEQ / AQ, H_HEADS, B_BATCH), 128, ATT_SMEM>>>(qkvb, Abf);

    // 4) Output projection (HMMA, 3-stage) -> out
    gemm_bf16_mma<0><<<dim3(D_MODEL / BN, M_ROWS / BM), 256, GEMM_SMEM>>>(
        Abf, Bout, b_out, out, nullptr, D_MODEL);
}

// round 10
// speedup vs baseline: 6.1025x; 1.2973x over previous
#include <cuda_runtime.h>
#include <cuda_fp16.h>
#include <math.h>
#include <stdint.h>

// ---------------------------------------------------------------------------
// Problem constants
// ---------------------------------------------------------------------------
#define D_MODEL 1024
#define H_HEADS 16
#define HD      64
#define B_BATCH 2
#define S_SEQ   2048
#define M_ROWS  (B_BATCH * S_SEQ)      // 4096
#define QKV_N   (3 * D_MODEL)          // 3072
#define KS2     (2 * D_MODEL)          // split-K: [hi | lo] of K=1024 (fp16)
#define QKV_E   (B_BATCH * H_HEADS * S_SEQ * HD)   // 4,194,304 per q/k/v

// ---------------------------------------------------------------------------
// Scratch (device globals — allocation-free)
// ---------------------------------------------------------------------------
__device__ __align__(256) __half g_Ah  [M_ROWS * KS2];      // A' = [hi|lo]
__device__ __align__(256) __half g_Bqkv[QKV_N  * D_MODEL];  // W_qkv^T fp16
__device__ __align__(256) __half g_Bout[D_MODEL * D_MODEL]; // W_out^T fp16
__device__ __align__(256) __half g_qkvh[3 * QKV_E];         // fp16 q|k|v [B,H,S,64]

// ---------------------------------------------------------------------------
// Helpers (portable PTX only: ldmatrix / mma.sync / cp.async)
// ---------------------------------------------------------------------------
__device__ __forceinline__ uint32_t smem_to_u32(const void* p) {
    uint32_t a;
    asm("{ .reg .u64 t; cvta.to.shared.u64 t, %1; cvt.u32.u64 %0, t; }"
        : "=r"(a) : "l"(p));
    return a;
}
__device__ __forceinline__ void cp_async16(uint32_t dst, const void* src) {
    asm volatile("cp.async.cg.shared.global [%0], [%1], 16;" :: "r"(dst), "l"(src));
}
__device__ __forceinline__ void cp_commit() { asm volatile("cp.async.commit_group;"); }
__device__ __forceinline__ void cp_wait1()  { asm volatile("cp.async.wait_group 1;"); }

__device__ __forceinline__ void ldsm_x4(uint32_t& r0, uint32_t& r1,
                                        uint32_t& r2, uint32_t& r3, uint32_t addr) {
    asm volatile("ldmatrix.sync.aligned.m8n8.x4.shared.b16 {%0,%1,%2,%3}, [%4];"
                 : "=r"(r0), "=r"(r1), "=r"(r2), "=r"(r3) : "r"(addr));
}
__device__ __forceinline__ void ldsm_x4_t(uint32_t& r0, uint32_t& r1,
                                          uint32_t& r2, uint32_t& r3, uint32_t addr) {
    asm volatile("ldmatrix.sync.aligned.m8n8.x4.trans.shared.b16 {%0,%1,%2,%3}, [%4];"
                 : "=r"(r0), "=r"(r1), "=r"(r2), "=r"(r3) : "r"(addr));
}
__device__ __forceinline__ void mma16816(float* c, const uint32_t* a, const uint32_t* b) {
    asm volatile("mma.sync.aligned.m16n8k16.row.col.f32.f16.f16.f32 "
                 "{%0,%1,%2,%3}, {%4,%5,%6,%7}, {%8,%9}, {%0,%1,%2,%3};"
                 : "+f"(c[0]), "+f"(c[1]), "+f"(c[2]), "+f"(c[3])
                 : "r"(a[0]), "r"(a[1]), "r"(a[2]), "r"(a[3]),
                   "r"(b[0]), "r"(b[1]));
}
__device__ __forceinline__ uint32_t packh2(float lo, float hi) {
    __half2 v = __floats2half2_rn(lo, hi);   // lo -> low 16 bits
    return *reinterpret_cast<uint32_t*>(&v);
}

// Swizzled byte offset of (row r, byte b within 128B row); XOR on 16B chunks.
#define SWZ(r, b) ((r) * 128 + ((b) ^ (((r) & 7) << 4)))

// ---------------------------------------------------------------------------
// Split conversion: fp32 [M,1024] -> fp16 [M, 2048] = [hi | lo]
// ---------------------------------------------------------------------------
__global__ void split_hi_lo_kernel(const float* __restrict__ in,
                                   __half* __restrict__ out)
{
    int idx = blockIdx.x * blockDim.x + threadIdx.x;   // one float4 per thread
    int m  = idx >> 8;
    int c4 = idx & 255;
    float4 v = *(const float4*)(in + ((size_t)m << 10) + c4 * 4);
    float vv[4] = {v.x, v.y, v.z, v.w};
    __half h[4], l[4];
    #pragma unroll
    for (int i = 0; i < 4; ++i) {
        h[i] = __float2half_rn(vv[i]);
        l[i] = __float2half_rn(vv[i] - __half2float(h[i]));
    }
    __half* base = out + (size_t)m * KS2 + c4 * 4;
    *(__half2*)(base + 0)        = __halves2half2(h[0], h[1]);
    *(__half2*)(base + 2)        = __halves2half2(h[2], h[3]);
    *(__half2*)(base + D_MODEL)     = __halves2half2(l[0], l[1]);
    *(__half2*)(base + D_MODEL + 2) = __halves2half2(l[2], l[3]);
}

// W [K=1024, N] row-major -> B' [N, 1024] fp16 (transpose + round)
__global__ void transpose_h_kernel(const float* __restrict__ W,
                                   __half* __restrict__ out, int N)
{
    __shared__ float tile[32][33];
    const int n0 = blockIdx.x * 32, k0 = blockIdx.y * 32;
    const int tx = threadIdx.x, ty = threadIdx.y;   // (32, 8)
    #pragma unroll
    for (int i = 0; i < 4; ++i)
        tile[ty + i * 8][tx] = W[(size_t)(k0 + ty + i * 8) * N + n0 + tx];
    __syncthreads();
    #pragma unroll
    for (int i = 0; i < 4; ++i) {
        const int n = n0 + ty + i * 8;
        const int k = k0 + tx;
        out[(size_t)n * D_MODEL + k] = __float2half_rn(tile[tx][ty + i * 8]);
    }
}

// ---------------------------------------------------------------------------
// Tensor-core GEMM via mma.sync (HMMA fp16), CTA 128x128, BK=64.
// C[M,N] = A'[M,2048] · Bh[N,1024]^T + bias  (B chunk index wraps: both A'
// sections [hi|lo] multiply the same Bh -> exact (Ah+Al)·Bh).
// 3-stage cp.async pipeline, one __syncthreads per chunk.
// MODE 0: fp32 C out.  MODE 1: qkv epilogue -> fp16 [3][B,H,S,64], q scaled.
// ---------------------------------------------------------------------------
#define BM 128
#define BN 128
#define BK 64
#define NCHUNK (KS2 / BK)                     // 32
#define BWRAP  (D_MODEL / BK - 1)             // 15 (mask for B chunk wrap)
#define STAGE_BYTES (BM * 128 + BN * 128)     // 32768
#define NSTAGE 3
#define GEMM_SMEM (NSTAGE * STAGE_BYTES)      // 98304

template <int MODE>
__global__ __launch_bounds__(256, 2)
void gemm_h_mma(const __half* __restrict__ A,
                const __half* __restrict__ B,
                const float* __restrict__ bias,
                float* __restrict__ C,
                __half* __restrict__ qkvh,
                int N)
{
    extern __shared__ char smem[];
    const uint32_t sb = smem_to_u32(smem);
    const int tid  = threadIdx.x;
    const int wid  = tid >> 5, lane = tid & 31;
    const int wm   = wid & 3;
    const int wn   = wid >> 2;
    const int m0   = blockIdx.y * BM;
    const int n0   = blockIdx.x * BN;

    const __half* Ab = A + (size_t)m0 * KS2;
    const __half* Bb = B + (size_t)n0 * D_MODEL;

    auto load_stage = [&](int kc, int s) {
        const uint32_t ab = sb + s * STAGE_BYTES;
        const uint32_t bb = ab + BM * 128;
        const int koffA = kc * BK;
        const int koffB = (kc & BWRAP) * BK;
        #pragma unroll
        for (int p = 0; p < 4; ++p) {
            const int idx = tid + p * 256;
            const int r = idx >> 3, q = idx & 7;
            cp_async16(ab + r * 128 + ((q ^ (r & 7)) << 4),
                       Ab + (size_t)r * KS2 + koffA + q * 8);
        }
        #pragma unroll
        for (int p = 0; p < 4; ++p) {
            const int idx = tid + p * 256;
            const int r = idx >> 3, q = idx & 7;
            cp_async16(bb + r * 128 + ((q ^ (r & 7)) << 4),
                       Bb + (size_t)r * D_MODEL + koffB + q * 8);
        }
    };

    float acc[2][8][4];
    #pragma unroll
    for (int mt = 0; mt < 2; ++mt)
        #pragma unroll
        for (int nt = 0; nt < 8; ++nt)
            #pragma unroll
            for (int i = 0; i < 4; ++i) acc[mt][nt][i] = 0.0f;

    load_stage(0, 0); cp_commit();
    load_stage(1, 1); cp_commit();

    int s = 0, ls = 2;                       // consume stage, load stage
    for (int kc = 0; kc < NCHUNK; ++kc) {
        cp_wait1();
        __syncthreads();                     // stage s ready; stage ls reads done

        const uint32_t ab = sb + s * STAGE_BYTES;
        const uint32_t bb = ab + BM * 128;

        #pragma unroll
        for (int ks = 0; ks < 4; ++ks) {
            const int kb = ks * 32;

            uint32_t av[2][4];
            #pragma unroll
            for (int mt = 0; mt < 2; ++mt) {
                const int r  = wm * 32 + mt * 16 + (lane & 15);
                const int cb = kb + ((lane >> 4) << 4);
                ldsm_x4(av[mt][0], av[mt][1], av[mt][2], av[mt][3],
                        ab + SWZ(r, cb));
            }
            uint32_t bv[8][2];
            #pragma unroll
            for (int nt2 = 0; nt2 < 4; ++nt2) {
                const int r  = wn * 64 + nt2 * 16 + (lane & 7) + ((lane >> 4) << 3);
                const int cb = kb + (((lane >> 3) & 1) << 4);
                uint32_t t0, t1, t2, t3;
                ldsm_x4(t0, t1, t2, t3, bb + SWZ(r, cb));
                bv[nt2 * 2][0] = t0;  bv[nt2 * 2][1] = t1;
                bv[nt2 * 2 + 1][0] = t2;  bv[nt2 * 2 + 1][1] = t3;
            }
            #pragma unroll
            for (int mt = 0; mt < 2; ++mt)
                #pragma unroll
                for (int nt = 0; nt < 8; ++nt)
                    mma16816(acc[mt][nt], av[mt], bv[nt]);
        }

        if (kc + 2 < NCHUNK) load_stage(kc + 2, ls);
        cp_commit();
        s  = (s  == NSTAGE - 1) ? 0 : s + 1;
        ls = (ls == NSTAGE - 1) ? 0 : ls + 1;
    }

    const int g  = lane >> 2;
    const int tg = lane & 3;
    #pragma unroll
    for (int mt = 0; mt < 2; ++mt) {
        const int row0 = m0 + wm * 32 + mt * 16 + g;
        #pragma unroll
        for (int nt = 0; nt < 8; ++nt) {
            const int col = n0 + wn * 64 + nt * 8 + tg * 2;
            const float2 bv = *(const float2*)(bias + col);
            float v0x = acc[mt][nt][0] + bv.x, v0y = acc[mt][nt][1] + bv.y;
            float v1x = acc[mt][nt][2] + bv.x, v1y = acc[mt][nt][3] + bv.y;
            if (MODE == 0) {
                *(float2*)(C + (size_t)row0 * N + col)       = make_float2(v0x, v0y);
                *(float2*)(C + (size_t)(row0 + 8) * N + col) = make_float2(v1x, v1y);
            } else {
                const int sec = col >> 10;
                const int hh  = (col >> 6) & 15;
                const int dd  = col & 63;
                const float sc = (sec == 0) ? 0.125f : 1.0f;   // fold 1/sqrt(64) into q
                __half* dst = qkvh + (size_t)sec * QKV_E;
                const size_t i0 = ((size_t)((row0 >> 11) * H_HEADS + hh) * S_SEQ
                                   + (row0 & 2047)) * HD + dd;
                const size_t i1 = ((size_t)(((row0 + 8) >> 11) * H_HEADS + hh) * S_SEQ
                                   + ((row0 + 8) & 2047)) * HD + dd;
                *(uint32_t*)(dst + i0) = packh2(v0x * sc, v0y * sc);
                *(uint32_t*)(dst + i1) = packh2(v1x * sc, v1y * sc);
            }
        }
    }
}

// ---------------------------------------------------------------------------
// Flash attention on tensor cores (mma.sync fp16, fp32 accum).
// 128 threads, 64 q-rows/CTA, Bc=64; 3-stage cp.async K/V, one sync per tile.
// Epilogue writes the hi/lo fp16 A' rows directly (fused split).
// ---------------------------------------------------------------------------
#define AQ 64
#define AK 64
#define AIT (S_SEQ / AK)          // 32
// dynamic smem: Q 8KB | K[3] 8KB each | V[3] 8KB each = 56 KB
#define SM_Q 0
#define SM_K 8192
#define SM_V (8192 + 3 * 8192)
#define ATT_SMEM (SM_V + 3 * 8192)   // 57344

__global__ __launch_bounds__(128)
void flash_attn_h(const __half* __restrict__ qkvh,
                  __half* __restrict__ Aout)
{
    extern __shared__ char sm[];
    const uint32_t sb = smem_to_u32(sm);
    const int tid = threadIdx.x, w = tid >> 5, lane = tid & 31;
    const int qt = blockIdx.x, h = blockIdx.y, b = blockIdx.z;

    const __half* qb = qkvh + ((size_t)(b * H_HEADS + h) * S_SEQ) * HD;
    const __half* kb = qb + QKV_E;
    const __half* vb = qb + 2 * (size_t)QKV_E;

    auto load_kv = [&](int t, int s) {
        const __half* ksrc = kb + (size_t)t * AK * HD;
        const __half* vsrc = vb + (size_t)t * AK * HD;
        #pragma unroll
        for (int p = 0; p < 4; ++p) {
            const int idx = tid + p * 128;
            const int r = idx >> 3, q = idx & 7;
            const uint32_t off = r * 128 + ((q ^ (r & 7)) << 4);
            cp_async16(sb + SM_K + s * 8192 + off, ksrc + (size_t)r * HD + q * 8);
            cp_async16(sb + SM_V + s * 8192 + off, vsrc + (size_t)r * HD + q * 8);
        }
    };

    // group0: Q + KV0 ; group1: KV1
    #pragma unroll
    for (int p = 0; p < 4; ++p) {
        const int idx = tid + p * 128;
        const int r = idx >> 3, q = idx & 7;
        cp_async16(sb + SM_Q + r * 128 + ((q ^ (r & 7)) << 4),
                   qb + (size_t)(qt * AQ + r) * HD + q * 8);
    }
    load_kv(0, 0); cp_commit();
    load_kv(1, 1); cp_commit();
    cp_wait1();
    __syncthreads();

    // Q fragments (persist)
    uint32_t qf[4][4];
    #pragma unroll
    for (int ks = 0; ks < 4; ++ks) {
        const int r  = w * 16 + (lane & 15);
        const int cb = ks * 32 + ((lane >> 4) << 4);
        ldsm_x4(qf[ks][0], qf[ks][1], qf[ks][2], qf[ks][3], sb + SM_Q + SWZ(r, cb));
    }

    float m2[2] = {-1e30f, -1e30f}, l2[2] = {0.0f, 0.0f};
    float oacc[8][4];
    #pragma unroll
    for (int nt = 0; nt < 8; ++nt)
        #pragma unroll
        for (int i = 0; i < 4; ++i) oacc[nt][i] = 0.0f;

    int s = 0, ls = 2;
    for (int t = 0; t < AIT; ++t) {
        if (t > 0) { cp_wait1(); __syncthreads(); }

        // ---- S = Q K^T ----
        float sacc[8][4];
        #pragma unroll
        for (int nt = 0; nt < 8; ++nt)
            #pragma unroll
            for (int i = 0; i < 4; ++i) sacc[nt][i] = 0.0f;

        const uint32_t kbuf = sb + SM_K + s * 8192;
        #pragma unroll
        for (int ks = 0; ks < 4; ++ks) {
            uint32_t bv[8][2];
            #pragma unroll
            for (int nt2 = 0; nt2 < 4; ++nt2) {
                const int r  = nt2 * 16 + (lane & 7) + ((lane >> 4) << 3);
                const int cb = ks * 32 + (((lane >> 3) & 1) << 4);
                uint32_t t0, t1, t2, t3;
                ldsm_x4(t0, t1, t2, t3, kbuf + SWZ(r, cb));
                bv[nt2 * 2][0] = t0;  bv[nt2 * 2][1] = t1;
                bv[nt2 * 2 + 1][0] = t2;  bv[nt2 * 2 + 1][1] = t3;
            }
            #pragma unroll
            for (int nt = 0; nt < 8; ++nt)
                mma16816(sacc[nt], qf[ks], bv[nt]);
        }

        // ---- online softmax ----
        #pragma unroll
        for (int hf = 0; hf < 2; ++hf) {
            float tmax = -1e30f;
            #pragma unroll
            for (int nt = 0; nt < 8; ++nt)
                tmax = fmaxf(tmax, fmaxf(sacc[nt][2 * hf], sacc[nt][2 * hf + 1]));
            tmax = fmaxf(tmax, __shfl_xor_sync(0xffffffffu, tmax, 1));
            tmax = fmaxf(tmax, __shfl_xor_sync(0xffffffffu, tmax, 2));

            const float mn    = fmaxf(m2[hf], tmax);
            const float alpha = __expf(m2[hf] - mn);
            m2[hf] = mn;

            float rs = 0.0f;
            #pragma unroll
            for (int nt = 0; nt < 8; ++nt) {
                const float p0 = __expf(sacc[nt][2 * hf]     - mn);
                const float p1 = __expf(sacc[nt][2 * hf + 1] - mn);
                sacc[nt][2 * hf] = p0;  sacc[nt][2 * hf + 1] = p1;
                rs += p0 + p1;
            }
            rs += __shfl_xor_sync(0xffffffffu, rs, 1);
            rs += __shfl_xor_sync(0xffffffffu, rs, 2);
            l2[hf] = l2[hf] * alpha + rs;

            #pragma unroll
            for (int nt = 0; nt < 8; ++nt) {
                oacc[nt][2 * hf]     *= alpha;
                oacc[nt][2 * hf + 1] *= alpha;
            }
        }

        // ---- P fragments (registers only) ----
        uint32_t pf[4][4];
        #pragma unroll
        for (int c = 0; c < 4; ++c) {
            pf[c][0] = packh2(sacc[2 * c][0],     sacc[2 * c][1]);
            pf[c][1] = packh2(sacc[2 * c][2],     sacc[2 * c][3]);
            pf[c][2] = packh2(sacc[2 * c + 1][0], sacc[2 * c + 1][1]);
            pf[c][3] = packh2(sacc[2 * c + 1][2], sacc[2 * c + 1][3]);
        }

        // ---- O += P V ----
        const uint32_t vbuf = sb + SM_V + s * 8192;
        #pragma unroll
        for (int ks = 0; ks < 4; ++ks) {
            uint32_t vv[8][2];
            #pragma unroll
            for (int ng = 0; ng < 4; ++ng) {
                const int r  = ks * 16 + (lane & 15);
                const int cb = ng * 32 + ((lane >> 4) << 4);
                uint32_t t0, t1, t2, t3;
                ldsm_x4_t(t0, t1, t2, t3, vbuf + SWZ(r, cb));
                vv[ng * 2][0] = t0;  vv[ng * 2][1] = t1;
                vv[ng * 2 + 1][0] = t2;  vv[ng * 2 + 1][1] = t3;
            }
            #pragma unroll
            for (int nt = 0; nt < 8; ++nt)
                mma16816(oacc[nt], pf[ks], vv[nt]);
        }

        if (t + 2 < AIT) load_kv(t + 2, ls);
        cp_commit();
        s  = (s  == 2) ? 0 : s + 1;
        ls = (ls == 2) ? 0 : ls + 1;
    }

    // ---- epilogue: normalize + fused hi/lo split into A' [row, 2048] ----
    const int g  = lane >> 2;
    const int tg = lane & 3;
    const float inv0 = __fdividef(1.0f, l2[0]);
    const float inv1 = __fdividef(1.0f, l2[1]);
    const int row0 = b * S_SEQ + qt * AQ + w * 16 + g;
    #pragma unroll
    for (int nt = 0; nt < 8; ++nt) {
        const int col = h * HD + nt * 8 + tg * 2;
        #pragma unroll
        for (int rr = 0; rr < 2; ++rr) {
            const float inv = rr ? inv1 : inv0;
            const float vx = oacc[nt][2 * rr]     * inv;
            const float vy = oacc[nt][2 * rr + 1] * inv;
            const __half hx = __float2half_rn(vx);
            const __half hy = __float2half_rn(vy);
            const __half lx = __float2half_rn(vx - __half2float(hx));
            const __half ly = __float2half_rn(vy - __half2float(hy));
            __half* dst = Aout + (size_t)(row0 + rr * 8) * KS2 + col;
            *(__half2*)(dst)           = __halves2half2(hx, hy);
            *(__half2*)(dst + D_MODEL) = __halves2half2(lx, ly);
        }
    }
}

// ---------------------------------------------------------------------------
// Launch
// ---------------------------------------------------------------------------
extern "C" void kernel_launch(void* const* d_in, const int* in_sizes, int n_in,
                              void* d_out, int out_size)
{
    const float* x     = (const float*)d_in[0];
    const float* W_qkv = (const float*)d_in[1];
    const float* b_qkv = (const float*)d_in[2];
    const float* W_out = (const float*)d_in[3];
    const float* b_out = (const float*)d_in[4];
    float* out = (float*)d_out;

    __half *Ah, *Bqkv, *Bout, *qkvh;
    cudaGetSymbolAddress((void**)&Ah,   g_Ah);
    cudaGetSymbolAddress((void**)&Bqkv, g_Bqkv);
    cudaGetSymbolAddress((void**)&Bout, g_Bout);
    cudaGetSymbolAddress((void**)&qkvh, g_qkvh);

    cudaFuncSetAttribute(gemm_h_mma<0>,
                         cudaFuncAttributeMaxDynamicSharedMemorySize, GEMM_SMEM);
    cudaFuncSetAttribute(gemm_h_mma<1>,
                         cudaFuncAttributeMaxDynamicSharedMemorySize, GEMM_SMEM);
    cudaFuncSetAttribute(flash_attn_h,
                         cudaFuncAttributeMaxDynamicSharedMemorySize, ATT_SMEM);

    // 1) convert inputs: x -> [hi|lo] fp16; weights -> transposed fp16
    split_hi_lo_kernel<<<M_ROWS, 256>>>(x, Ah);
    transpose_h_kernel<<<dim3(QKV_N / 32, D_MODEL / 32), dim3(32, 8)>>>(W_qkv, Bqkv, QKV_N);
    transpose_h_kernel<<<dim3(D_MODEL / 32, D_MODEL / 32), dim3(32, 8)>>>(W_out, Bout, D_MODEL);

    // 2) QKV projection (HMMA fp16, 2-term) -> fp16 q|k|v [B,H,S,64], q scaled
    gemm_h_mma<1><<<dim3(QKV_N / BN, M_ROWS / BM), 256, GEMM_SMEM>>>(
        Ah, Bqkv, b_qkv, nullptr, qkvh, QKV_N);

    // 3) Flash attention (HMMA fp16) -> fused hi/lo split into A'
    flash_attn_h<<<dim3(S_SEQ / AQ, H_HEADS, B_BATCH), 128, ATT_SMEM>>>(qkvh, Ah);

    // 4) Output projection (HMMA fp16, 2-term) -> out
    gemm_h_mma<0><<<dim3(D_MODEL / BN, M_ROWS / BM), 256, GEMM_SMEM>>>(
        Ah, Bout, b_out, out, nullptr, D_MODEL);
}

// round 11
// speedup vs baseline: 7.7438x; 1.2690x over previous
#include <cuda_runtime.h>
#include <cuda_fp16.h>
#include <math.h>
#include <stdint.h>

// ---------------------------------------------------------------------------
// Problem constants
// ---------------------------------------------------------------------------
#define D_MODEL 1024
#define H_HEADS 16
#define HD      64
#define B_BATCH 2
#define S_SEQ   2048
#define M_ROWS  (B_BATCH * S_SEQ)      // 4096
#define QKV_N   (3 * D_MODEL)          // 3072
#define QKV_E   (B_BATCH * H_HEADS * S_SEQ * HD)   // 4,194,304 per q/k/v

// ---------------------------------------------------------------------------
// Scratch (device globals — allocation-free)
// ---------------------------------------------------------------------------
__device__ __align__(256) __half g_Ah  [M_ROWS * D_MODEL];  // fp16 activations
__device__ __align__(256) __half g_Bqkv[QKV_N  * D_MODEL];  // W_qkv^T fp16
__device__ __align__(256) __half g_Bout[D_MODEL * D_MODEL]; // W_out^T fp16
__device__ __align__(256) __half g_qkvh[3 * QKV_E];         // fp16 q|k|v [B,H,S,64]

// ---------------------------------------------------------------------------
// Helpers (portable PTX only: ldmatrix / mma.sync / cp.async)
// ---------------------------------------------------------------------------
__device__ __forceinline__ uint32_t smem_to_u32(const void* p) {
    uint32_t a;
    asm("{ .reg .u64 t; cvta.to.shared.u64 t, %1; cvt.u32.u64 %0, t; }"
        : "=r"(a) : "l"(p));
    return a;
}
__device__ __forceinline__ void cp_async16(uint32_t dst, const void* src) {
    asm volatile("cp.async.cg.shared.global [%0], [%1], 16;" :: "r"(dst), "l"(src));
}
__device__ __forceinline__ void cp_commit() { asm volatile("cp.async.commit_group;"); }
__device__ __forceinline__ void cp_wait1()  { asm volatile("cp.async.wait_group 1;"); }

__device__ __forceinline__ void ldsm_x4(uint32_t& r0, uint32_t& r1,
                                        uint32_t& r2, uint32_t& r3, uint32_t addr) {
    asm volatile("ldmatrix.sync.aligned.m8n8.x4.shared.b16 {%0,%1,%2,%3}, [%4];"
                 : "=r"(r0), "=r"(r1), "=r"(r2), "=r"(r3) : "r"(addr));
}
__device__ __forceinline__ void ldsm_x4_t(uint32_t& r0, uint32_t& r1,
                                          uint32_t& r2, uint32_t& r3, uint32_t addr) {
    asm volatile("ldmatrix.sync.aligned.m8n8.x4.trans.shared.b16 {%0,%1,%2,%3}, [%4];"
                 : "=r"(r0), "=r"(r1), "=r"(r2), "=r"(r3) : "r"(addr));
}
__device__ __forceinline__ void mma16816(float* c, const uint32_t* a, const uint32_t* b) {
    asm volatile("mma.sync.aligned.m16n8k16.row.col.f32.f16.f16.f32 "
                 "{%0,%1,%2,%3}, {%4,%5,%6,%7}, {%8,%9}, {%0,%1,%2,%3};"
                 : "+f"(c[0]), "+f"(c[1]), "+f"(c[2]), "+f"(c[3])
                 : "r"(a[0]), "r"(a[1]), "r"(a[2]), "r"(a[3]),
                   "r"(b[0]), "r"(b[1]));
}
__device__ __forceinline__ uint32_t packh2(float lo, float hi) {
    __half2 v = __floats2half2_rn(lo, hi);   // lo -> low 16 bits
    return *reinterpret_cast<uint32_t*>(&v);
}

// Swizzled byte offset of (row r, byte b within 128B row); XOR on 16B chunks.
#define SWZ(r, b) ((r) * 128 + ((b) ^ (((r) & 7) << 4)))

// ---------------------------------------------------------------------------
// Convert: fp32 [M,1024] -> fp16 [M,1024]
// ---------------------------------------------------------------------------
__global__ void convert_h_kernel(const float* __restrict__ in,
                                 __half* __restrict__ out)
{
    const int idx = blockIdx.x * blockDim.x + threadIdx.x;   // one float4
    float4 v = *(const float4*)(in + (size_t)idx * 4);
    __half2 a = __floats2half2_rn(v.x, v.y);
    __half2 b = __floats2half2_rn(v.z, v.w);
    *(__half2*)(out + (size_t)idx * 4)     = a;
    *(__half2*)(out + (size_t)idx * 4 + 2) = b;
}

// W [K=1024, N] row-major -> B' [N, 1024] fp16 (transpose + round)
__global__ void transpose_h_kernel(const float* __restrict__ W,
                                   __half* __restrict__ out, int N)
{
    __shared__ float tile[32][33];
    const int n0 = blockIdx.x * 32, k0 = blockIdx.y * 32;
    const int tx = threadIdx.x, ty = threadIdx.y;   // (32, 8)
    #pragma unroll
    for (int i = 0; i < 4; ++i)
        tile[ty + i * 8][tx] = W[(size_t)(k0 + ty + i * 8) * N + n0 + tx];
    __syncthreads();
    #pragma unroll
    for (int i = 0; i < 4; ++i) {
        const int n = n0 + ty + i * 8;
        const int k = k0 + tx;
        out[(size_t)n * D_MODEL + k] = __float2half_rn(tile[tx][ty + i * 8]);
    }
}

// ---------------------------------------------------------------------------
// Tensor-core GEMM via mma.sync (HMMA fp16), CTA 128x128, BK=64, K=1024.
// 3-stage cp.async pipeline, one __syncthreads per chunk.
// MODE 0: fp32 C out.  MODE 1: qkv epilogue -> fp16 [3][B,H,S,64], q scaled.
// ---------------------------------------------------------------------------
#define BM 128
#define BN 128
#define BK 64
#define NCHUNK (D_MODEL / BK)                 // 16
#define STAGE_BYTES (BM * 128 + BN * 128)     // 32768
#define NSTAGE 3
#define GEMM_SMEM (NSTAGE * STAGE_BYTES)      // 98304

template <int MODE>
__global__ __launch_bounds__(256, 2)
void gemm_h_mma(const __half* __restrict__ A,
                const __half* __restrict__ B,
                const float* __restrict__ bias,
                float* __restrict__ C,
                __half* __restrict__ qkvh,
                int N)
{
    extern __shared__ char smem[];
    const uint32_t sb = smem_to_u32(smem);
    const int tid  = threadIdx.x;
    const int wid  = tid >> 5, lane = tid & 31;
    const int wm   = wid & 3;
    const int wn   = wid >> 2;
    const int m0   = blockIdx.y * BM;
    const int n0   = blockIdx.x * BN;

    const __half* Ab = A + (size_t)m0 * D_MODEL;
    const __half* Bb = B + (size_t)n0 * D_MODEL;

    auto load_stage = [&](int kc, int s) {
        const uint32_t ab = sb + s * STAGE_BYTES;
        const uint32_t bb = ab + BM * 128;
        const int koff = kc * BK;
        #pragma unroll
        for (int p = 0; p < 4; ++p) {
            const int idx = tid + p * 256;
            const int r = idx >> 3, q = idx & 7;
            cp_async16(ab + r * 128 + ((q ^ (r & 7)) << 4),
                       Ab + (size_t)r * D_MODEL + koff + q * 8);
        }
        #pragma unroll
        for (int p = 0; p < 4; ++p) {
            const int idx = tid + p * 256;
            const int r = idx >> 3, q = idx & 7;
            cp_async16(bb + r * 128 + ((q ^ (r & 7)) << 4),
                       Bb + (size_t)r * D_MODEL + koff + q * 8);
        }
    };

    float acc[2][8][4];
    #pragma unroll
    for (int mt = 0; mt < 2; ++mt)
        #pragma unroll
        for (int nt = 0; nt < 8; ++nt)
            #pragma unroll
            for (int i = 0; i < 4; ++i) acc[mt][nt][i] = 0.0f;

    load_stage(0, 0); cp_commit();
    load_stage(1, 1); cp_commit();

    int s = 0, ls = 2;                       // consume stage, load stage
    for (int kc = 0; kc < NCHUNK; ++kc) {
        cp_wait1();
        __syncthreads();                     // stage s ready; stage ls reads done

        const uint32_t ab = sb + s * STAGE_BYTES;
        const uint32_t bb = ab + BM * 128;

        #pragma unroll
        for (int ks = 0; ks < 4; ++ks) {
            const int kb = ks * 32;

            uint32_t av[2][4];
            #pragma unroll
            for (int mt = 0; mt < 2; ++mt) {
                const int r  = wm * 32 + mt * 16 + (lane & 15);
                const int cb = kb + ((lane >> 4) << 4);
                ldsm_x4(av[mt][0], av[mt][1], av[mt][2], av[mt][3],
                        ab + SWZ(r, cb));
            }
            uint32_t bv[8][2];
            #pragma unroll
            for (int nt2 = 0; nt2 < 4; ++nt2) {
                const int r  = wn * 64 + nt2 * 16 + (lane & 7) + ((lane >> 4) << 3);
                const int cb = kb + (((lane >> 3) & 1) << 4);
                uint32_t t0, t1, t2, t3;
                ldsm_x4(t0, t1, t2, t3, bb + SWZ(r, cb));
                bv[nt2 * 2][0] = t0;  bv[nt2 * 2][1] = t1;
                bv[nt2 * 2 + 1][0] = t2;  bv[nt2 * 2 + 1][1] = t3;
            }
            #pragma unroll
            for (int mt = 0; mt < 2; ++mt)
                #pragma unroll
                for (int nt = 0; nt < 8; ++nt)
                    mma16816(acc[mt][nt], av[mt], bv[nt]);
        }

        if (kc + 2 < NCHUNK) load_stage(kc + 2, ls);
        cp_commit();
        s  = (s  == NSTAGE - 1) ? 0 : s + 1;
        ls = (ls == NSTAGE - 1) ? 0 : ls + 1;
    }

    const int g  = lane >> 2;
    const int tg = lane & 3;
    #pragma unroll
    for (int mt = 0; mt < 2; ++mt) {
        const int row0 = m0 + wm * 32 + mt * 16 + g;
        #pragma unroll
        for (int nt = 0; nt < 8; ++nt) {
            const int col = n0 + wn * 64 + nt * 8 + tg * 2;
            const float2 bv = *(const float2*)(bias + col);
            float v0x = acc[mt][nt][0] + bv.x, v0y = acc[mt][nt][1] + bv.y;
            float v1x = acc[mt][nt][2] + bv.x, v1y = acc[mt][nt][3] + bv.y;
            if (MODE == 0) {
                *(float2*)(C + (size_t)row0 * N + col)       = make_float2(v0x, v0y);
                *(float2*)(C + (size_t)(row0 + 8) * N + col) = make_float2(v1x, v1y);
            } else {
                const int sec = col >> 10;
                const int hh  = (col >> 6) & 15;
                const int dd  = col & 63;
                const float sc = (sec == 0) ? 0.125f : 1.0f;   // fold 1/sqrt(64) into q
                __half* dst = qkvh + (size_t)sec * QKV_E;
                const size_t i0 = ((size_t)((row0 >> 11) * H_HEADS + hh) * S_SEQ
                                   + (row0 & 2047)) * HD + dd;
                const size_t i1 = ((size_t)(((row0 + 8) >> 11) * H_HEADS + hh) * S_SEQ
                                   + ((row0 + 8) & 2047)) * HD + dd;
                *(uint32_t*)(dst + i0) = packh2(v0x * sc, v0y * sc);
                *(uint32_t*)(dst + i1) = packh2(v1x * sc, v1y * sc);
            }
        }
    }
}

// ---------------------------------------------------------------------------
// Flash attention on tensor cores (mma.sync fp16, fp32 accum).
// 256 threads (8 warps), 128 q-rows/CTA (halves K/V L2 traffic vs AQ=64),
// Bc=64; 3-stage cp.async K/V, one sync per tile. Warp w owns rows w*16..+15.
// Epilogue writes fp16 A rows directly.
// ---------------------------------------------------------------------------
#define AQ 128
#define AK 64
#define AIT (S_SEQ / AK)          // 32
// dynamic smem: Q 16KB | K[3] 8KB each | V[3] 8KB each = 64 KB
#define SM_Q 0
#define SM_K 16384
#define SM_V (16384 + 3 * 8192)
#define ATT_SMEM (SM_V + 3 * 8192)   // 65536

__global__ __launch_bounds__(256)
void flash_attn_h(const __half* __restrict__ qkvh,
                  __half* __restrict__ Aout)
{
    extern __shared__ char sm[];
    const uint32_t sb = smem_to_u32(sm);
    const int tid = threadIdx.x, w = tid >> 5, lane = tid & 31;
    const int qt = blockIdx.x, h = blockIdx.y, b = blockIdx.z;

    const __half* qb = qkvh + ((size_t)(b * H_HEADS + h) * S_SEQ) * HD;
    const __half* kb = qb + QKV_E;
    const __half* vb = qb + 2 * (size_t)QKV_E;

    auto load_kv = [&](int t, int s) {
        const __half* ksrc = kb + (size_t)t * AK * HD;
        const __half* vsrc = vb + (size_t)t * AK * HD;
        #pragma unroll
        for (int p = 0; p < 2; ++p) {
            const int idx = tid + p * 256;
            const int r = idx >> 3, q = idx & 7;
            const uint32_t off = r * 128 + ((q ^ (r & 7)) << 4);
            cp_async16(sb + SM_K + s * 8192 + off, ksrc + (size_t)r * HD + q * 8);
            cp_async16(sb + SM_V + s * 8192 + off, vsrc + (size_t)r * HD + q * 8);
        }
    };

    // group0: Q + KV0 ; group1: KV1
    #pragma unroll
    for (int p = 0; p < 4; ++p) {
        const int idx = tid + p * 256;
        const int r = idx >> 3, q = idx & 7;
        cp_async16(sb + SM_Q + r * 128 + ((q ^ (r & 7)) << 4),
                   qb + (size_t)(qt * AQ + r) * HD + q * 8);
    }
    load_kv(0, 0); cp_commit();
    load_kv(1, 1); cp_commit();
    cp_wait1();
    __syncthreads();

    // Q fragments (persist): warp w's 16 rows
    uint32_t qf[4][4];
    #pragma unroll
    for (int ks = 0; ks < 4; ++ks) {
        const int r  = w * 16 + (lane & 15);
        const int cb = ks * 32 + ((lane >> 4) << 4);
        ldsm_x4(qf[ks][0], qf[ks][1], qf[ks][2], qf[ks][3], sb + SM_Q + SWZ(r, cb));
    }

    float m2[2] = {-1e30f, -1e30f}, l2[2] = {0.0f, 0.0f};
    float oacc[8][4];
    #pragma unroll
    for (int nt = 0; nt < 8; ++nt)
        #pragma unroll
        for (int i = 0; i < 4; ++i) oacc[nt][i] = 0.0f;

    int s = 0, ls = 2;
    for (int t = 0; t < AIT; ++t) {
        if (t > 0) { cp_wait1(); __syncthreads(); }

        // ---- S = Q K^T ----
        float sacc[8][4];
        #pragma unroll
        for (int nt = 0; nt < 8; ++nt)
            #pragma unroll
            for (int i = 0; i < 4; ++i) sacc[nt][i] = 0.0f;

        const uint32_t kbuf = sb + SM_K + s * 8192;
        #pragma unroll
        for (int ks = 0; ks < 4; ++ks) {
            uint32_t bv[8][2];
            #pragma unroll
            for (int nt2 = 0; nt2 < 4; ++nt2) {
                const int r  = nt2 * 16 + (lane & 7) + ((lane >> 4) << 3);
                const int cb = ks * 32 + (((lane >> 3) & 1) << 4);
                uint32_t t0, t1, t2, t3;
                ldsm_x4(t0, t1, t2, t3, kbuf + SWZ(r, cb));
                bv[nt2 * 2][0] = t0;  bv[nt2 * 2][1] = t1;
                bv[nt2 * 2 + 1][0] = t2;  bv[nt2 * 2 + 1][1] = t3;
            }
            #pragma unroll
            for (int nt = 0; nt < 8; ++nt)
                mma16816(sacc[nt], qf[ks], bv[nt]);
        }

        // ---- online softmax ----
        #pragma unroll
        for (int hf = 0; hf < 2; ++hf) {
            float tmax = -1e30f;
            #pragma unroll
            for (int nt = 0; nt < 8; ++nt)
                tmax = fmaxf(tmax, fmaxf(sacc[nt][2 * hf], sacc[nt][2 * hf + 1]));
            tmax = fmaxf(tmax, __shfl_xor_sync(0xffffffffu, tmax, 1));
            tmax = fmaxf(tmax, __shfl_xor_sync(0xffffffffu, tmax, 2));

            const float mn    = fmaxf(m2[hf], tmax);
            const float alpha = __expf(m2[hf] - mn);
            m2[hf] = mn;

            float rs = 0.0f;
            #pragma unroll
            for (int nt = 0; nt < 8; ++nt) {
                const float p0 = __expf(sacc[nt][2 * hf]     - mn);
                const float p1 = __expf(sacc[nt][2 * hf + 1] - mn);
                sacc[nt][2 * hf] = p0;  sacc[nt][2 * hf + 1] = p1;
                rs += p0 + p1;
            }
            rs += __shfl_xor_sync(0xffffffffu, rs, 1);
            rs += __shfl_xor_sync(0xffffffffu, rs, 2);
            l2[hf] = l2[hf] * alpha + rs;

            #pragma unroll
            for (int nt = 0; nt < 8; ++nt) {
                oacc[nt][2 * hf]     *= alpha;
                oacc[nt][2 * hf + 1] *= alpha;
            }
        }

        // ---- P fragments (registers only) ----
        uint32_t pf[4][4];
        #pragma unroll
        for (int c = 0; c < 4; ++c) {
            pf[c][0] = packh2(sacc[2 * c][0],     sacc[2 * c][1]);
            pf[c][1] = packh2(sacc[2 * c][2],     sacc[2 * c][3]);
            pf[c][2] = packh2(sacc[2 * c + 1][0], sacc[2 * c + 1][1]);
            pf[c][3] = packh2(sacc[2 * c + 1][2], sacc[2 * c + 1][3]);
        }

        // ---- O += P V ----
        const uint32_t vbuf = sb + SM_V + s * 8192;
        #pragma unroll
        for (int ks = 0; ks < 4; ++ks) {
            uint32_t vv[8][2];
            #pragma unroll
            for (int ng = 0; ng < 4; ++ng) {
                const int r  = ks * 16 + (lane & 15);
                const int cb = ng * 32 + ((lane >> 4) << 4);
                uint32_t t0, t1, t2, t3;
                ldsm_x4_t(t0, t1, t2, t3, vbuf + SWZ(r, cb));
                vv[ng * 2][0] = t0;  vv[ng * 2][1] = t1;
                vv[ng * 2 + 1][0] = t2;  vv[ng * 2 + 1][1] = t3;
            }
            #pragma unroll
            for (int nt = 0; nt < 8; ++nt)
                mma16816(oacc[nt], pf[ks], vv[nt]);
        }

        if (t + 2 < AIT) load_kv(t + 2, ls);
        cp_commit();
        s  = (s  == 2) ? 0 : s + 1;
        ls = (ls == 2) ? 0 : ls + 1;
    }

    // ---- epilogue: normalize, write fp16 A rows [M,1024] at col h*64+d ----
    const int g  = lane >> 2;
    const int tg = lane & 3;
    const float inv0 = __fdividef(1.0f, l2[0]);
    const float inv1 = __fdividef(1.0f, l2[1]);
    const int row0 = b * S_SEQ + qt * AQ + w * 16 + g;
    #pragma unroll
    for (int nt = 0; nt < 8; ++nt) {
        const int col = h * HD + nt * 8 + tg * 2;
        *(uint32_t*)(Aout + (size_t)row0 * D_MODEL + col) =
            packh2(oacc[nt][0] * inv0, oacc[nt][1] * inv0);
        *(uint32_t*)(Aout + (size_t)(row0 + 8) * D_MODEL + col) =
            packh2(oacc[nt][2] * inv1, oacc[nt][3] * inv1);
    }
}

// ---------------------------------------------------------------------------
// Launch
// ---------------------------------------------------------------------------
extern "C" void kernel_launch(void* const* d_in, const int* in_sizes, int n_in,
                              void* d_out, int out_size)
{
    const float* x     = (const float*)d_in[0];
    const float* W_qkv = (const float*)d_in[1];
    const float* b_qkv = (const float*)d_in[2];
    const float* W_out = (const float*)d_in[3];
    const float* b_out = (const float*)d_in[4];
    float* out = (float*)d_out;

    __half *Ah, *Bqkv, *Bout, *qkvh;
    cudaGetSymbolAddress((void**)&Ah,   g_Ah);
    cudaGetSymbolAddress((void**)&Bqkv, g_Bqkv);
    cudaGetSymbolAddress((void**)&Bout, g_Bout);
    cudaGetSymbolAddress((void**)&qkvh, g_qkvh);

    cudaFuncSetAttribute(gemm_h_mma<0>,
                         cudaFuncAttributeMaxDynamicSharedMemorySize, GEMM_SMEM);
    cudaFuncSetAttribute(gemm_h_mma<1>,
                         cudaFuncAttributeMaxDynamicSharedMemorySize, GEMM_SMEM);
    cudaFuncSetAttribute(flash_attn_h,
                         cudaFuncAttributeMaxDynamicSharedMemorySize, ATT_SMEM);

    // 1) convert inputs: x -> fp16; weights -> transposed fp16
    convert_h_kernel<<<(M_ROWS * D_MODEL) / (256 * 4), 256>>>(x, Ah);
    transpose_h_kernel<<<dim3(QKV_N / 32, D_MODEL / 32), dim3(32, 8)>>>(W_qkv, Bqkv, QKV_N);
    transpose_h_kernel<<<dim3(D_MODEL / 32, D_MODEL / 32), dim3(32, 8)>>>(W_out, Bout, D_MODEL);

    // 2) QKV projection (HMMA fp16, K=1024) -> fp16 q|k|v [B,H,S,64], q scaled
    gemm_h_mma<1><<<dim3(QKV_N / BN, M_ROWS / BM), 256, GEMM_SMEM>>>(
        Ah, Bqkv, b_qkv, nullptr, qkvh, QKV_N);

    // 3) Flash attention (HMMA fp16, 128 q-rows/CTA) -> fp16 A
    flash_attn_h<<<dim3(S_SEQ / AQ, H_HEADS, B_BATCH), 256, ATT_SMEM>>>(qkvh, Ah);

    // 4) Output projection (HMMA fp16, K=1024) -> out
    gemm_h_mma<0><<<dim3(D_MODEL / BN, M_ROWS / BM), 256, GEMM_SMEM>>>(
        Ah, Bout, b_out, out, nullptr, D_MODEL);
}